// round 5
// baseline (speedup 1.0000x reference)
#include <cuda_runtime.h>
#include <cuda_bf16.h>
#include <math.h>
#include <stdint.h>

#define NN   50000
#define NE   800000
#define D_IN 128
#define D_HID 256
#define D_OUT 128
#define NL   8

// ---------------- weight buffer layout (transposed, K-major [N][K]) ------
#define WB_L1   0                         // lin1: [256][128]
#define WB_LYR  32768                     // layers: 8 x [256][512]  (W' = beta*W + omb*I)
#define WB_L2   (32768 + 8 * 131072)      // lin2: [128][256]
#define WB_TOT  (WB_L2 + 32768)

// ------------------------- static device scratch -------------------------
__device__ float  g_dis[NN];
__device__ int    g_rowptr[NN + 1];
__device__ int    g_cnt[NN];
__device__ int    g_bsum[64];
__device__ int    g_boff[64];
__device__ int    g_src[NE];
__device__ float  g_w[NE];
__device__ float  g_x0[(size_t)NN * D_HID];
__device__ float  g_h [(size_t)NN * D_HID];
__device__ float  g_r [(size_t)NN * D_HID];
__device__ double g_accA[2][2];           // [parity][sum, sumsq]
// bf16 split operands
__device__ __nv_bfloat16 g_A_hi[(size_t)NN * 512];   // cols 0..255: t (or h_norm) ; 256..511: 0.5*x0
__device__ __nv_bfloat16 g_A_lo[(size_t)NN * 512];
__device__ __nv_bfloat16 g_xin_hi[(size_t)NN * D_IN];
__device__ __nv_bfloat16 g_xin_lo[(size_t)NN * D_IN];
__device__ __nv_bfloat16 g_Bw_hi[WB_TOT];
__device__ __nv_bfloat16 g_Bw_lo[WB_TOT];

// ------------------------- helpers -------------------------
__device__ __forceinline__ uint32_t smem_u32(const void* p) {
    uint32_t a;
    asm("{ .reg .u64 t; cvta.to.shared.u64 t, %1; cvt.u32.u64 %0, t; }" : "=r"(a) : "l"(p));
    return a;
}
__device__ __forceinline__ void cp16(uint32_t dst, const void* src) {
    asm volatile("cp.async.cg.shared.global [%0], [%1], 16;" :: "r"(dst), "l"(src));
}
#define CP_COMMIT() asm volatile("cp.async.commit_group;" ::: "memory")
#define CP_WAIT1()  asm volatile("cp.async.wait_group 1;" ::: "memory")

__device__ __forceinline__ void ldm_x4(uint32_t* r, uint32_t addr) {
    asm volatile("ldmatrix.sync.aligned.m8n8.x4.shared.b16 {%0,%1,%2,%3}, [%4];"
                 : "=r"(r[0]), "=r"(r[1]), "=r"(r[2]), "=r"(r[3]) : "r"(addr));
}
__device__ __forceinline__ void ldm_x2(uint32_t* r, uint32_t addr) {
    asm volatile("ldmatrix.sync.aligned.m8n8.x2.shared.b16 {%0,%1}, [%2];"
                 : "=r"(r[0]), "=r"(r[1]) : "r"(addr));
}
__device__ __forceinline__ void mma16816(float* c, const uint32_t* a, const uint32_t* b) {
    asm volatile("mma.sync.aligned.m16n8k16.row.col.f32.bf16.bf16.f32 "
                 "{%0,%1,%2,%3}, {%4,%5,%6,%7}, {%8,%9}, {%0,%1,%2,%3};"
                 : "+f"(c[0]), "+f"(c[1]), "+f"(c[2]), "+f"(c[3])
                 : "r"(a[0]), "r"(a[1]), "r"(a[2]), "r"(a[3]), "r"(b[0]), "r"(b[1]));
}
__device__ __forceinline__ void split2(float v, __nv_bfloat16& h, __nv_bfloat16& l) {
    h = __float2bfloat16(v);
    l = __float2bfloat16(v - __bfloat162float(h));
}

// ------------------------- setup kernels -------------------------
__global__ void k_init() {
    int i = blockIdx.x * blockDim.x + threadIdx.x;
    if (i < NN) { g_dis[i] = 1.0f; g_cnt[i] = 0; }
}
__global__ void k_edge_count(const int* __restrict__ ei) {
    int e = blockIdx.x * blockDim.x + threadIdx.x;
    if (e < NE) {
        int c = ei[NE + e];
        atomicAdd(&g_dis[c], 1.0f);
        atomicAdd(&g_cnt[c], 1);
    }
}
__global__ void k_rsqrt() {
    int i = blockIdx.x * blockDim.x + threadIdx.x;
    if (i < NN) g_dis[i] = rsqrtf(g_dis[i]);
}
__device__ __forceinline__ int block_scan_inc(int v, int* wsum) {
    int lane = threadIdx.x & 31, wid = threadIdx.x >> 5;
#pragma unroll
    for (int o = 1; o < 32; o <<= 1) { int t = __shfl_up_sync(~0u, v, o); if (lane >= o) v += t; }
    if (lane == 31) wsum[wid] = v;
    __syncthreads();
    if (wid == 0) {
        int w = wsum[lane];
#pragma unroll
        for (int o = 1; o < 32; o <<= 1) { int t = __shfl_up_sync(~0u, w, o); if (lane >= o) w += t; }
        wsum[lane] = w;
    }
    __syncthreads();
    return v + (wid > 0 ? wsum[wid - 1] : 0);
}
__global__ void k_scan_part() {
    __shared__ int wsum[32];
    int i = blockIdx.x * 1024 + threadIdx.x;
    int v = (i < NN) ? g_cnt[i] : 0;
    int inc = block_scan_inc(v, wsum);
    if (threadIdx.x == 1023) g_bsum[blockIdx.x] = inc;
}
__global__ void k_scan_top() {
    if (threadIdx.x == 0) {
        int run = 0;
        for (int b = 0; b < 49; b++) { g_boff[b] = run; run += g_bsum[b]; }
        g_rowptr[NN] = run;
    }
}
__global__ void k_scan_out() {
    __shared__ int wsum[32];
    int i = blockIdx.x * 1024 + threadIdx.x;
    int v = (i < NN) ? g_cnt[i] : 0;
    int inc = block_scan_inc(v, wsum);
    if (i < NN) g_rowptr[i] = g_boff[blockIdx.x] + inc - v;   // exclusive
}
__global__ void k_cursor() {
    int i = blockIdx.x * blockDim.x + threadIdx.x;
    if (i < NN) g_cnt[i] = g_rowptr[i];
}
__global__ void k_scatter(const int* __restrict__ ei) {
    int e = blockIdx.x * blockDim.x + threadIdx.x;
    if (e < NE) {
        int r = ei[e];
        int c = ei[NE + e];
        int s = atomicAdd(&g_cnt[c], 1);
        g_src[s] = r;
        g_w[s]   = g_dis[r] * g_dis[c];
    }
}

// ------------------------- weight / input prep (bf16 splits) -------------
__global__ void k_prep_w(const float* __restrict__ lin1_w, const float* __restrict__ w1,
                         const float* __restrict__ w2, const float* __restrict__ lin2_w) {
    int idx = blockIdx.x * blockDim.x + threadIdx.x;
    if (idx >= WB_TOT) return;
    float v;
    if (idx < WB_LYR) {                       // lin1: [n=256][k=128]
        int n = idx >> 7, k = idx & 127;
        v = lin1_w[k * 256 + n];
    } else if (idx < WB_L2) {                 // layer l: [n=256][k=512]
        int r = idx - WB_LYR;
        int l = r >> 17;
        int q = r & 131071;
        int n = q >> 9, k = q & 511;
        float beta = logf((float)(l + 2) / (float)(l + 1));
        float omb = 1.0f - beta;
        if (k < 256) v = beta * w1[l * 65536 + k * 256 + n] + ((k == n) ? omb : 0.0f);
        else {
            int k2 = k - 256;
            v = beta * w2[l * 65536 + k2 * 256 + n] + ((k2 == n) ? omb : 0.0f);
        }
    } else {                                  // lin2: [n=128][k=256]
        int r = idx - WB_L2;
        int n = r >> 8, k = r & 255;
        v = lin2_w[k * 128 + n];
    }
    __nv_bfloat16 h, l;
    split2(v, h, l);
    g_Bw_hi[idx] = h;
    g_Bw_lo[idx] = l;
}
__global__ void k_prep_x(const float* __restrict__ x) {
    size_t idx = (size_t)blockIdx.x * blockDim.x + threadIdx.x;
    if (idx >= (size_t)NN * D_IN) return;
    __nv_bfloat16 h, l;
    split2(x[idx], h, l);
    g_xin_hi[idx] = h;
    g_xin_lo[idx] = l;
}

// ------------------------- mixed kernel: SpMM + GEMM_r -------------------
// grid = 3912 blocks of 512 threads. b%5==4 -> GEMM_r tile q=b/5 (782 tiles);
// else SpMM for 16 nodes (sid = q*4 + b%5).
// GEMM_r: g_r[tile] = (0.5*x0) @ W2'  (A = g_A cols 256..511, K=256)
// SpMM: t = 0.5 * Ahat eta(h_prev) -> bf16 splits into g_A cols 0..255
#define STG_SZ 40960
#define NSTG 3
#define SM_TOTAL (NSTG * STG_SZ)

__global__ void __launch_bounds__(512) k_mix(int l, const float* __restrict__ gam,
                                             const float* __restrict__ bet, int bOff) {
    extern __shared__ char smem[];
    int b = blockIdx.x, q = b / 5, rr = b % 5;
    int tid = threadIdx.x;
    int lane = tid & 31, wrp = tid >> 5;

    if (rr == 4) {
        // ================= GEMM_r (16 warps, 128x128, K=256) =================
        uint32_t sb = smem_u32(smem);
        int wm = wrp & 3, wn = wrp >> 2;
        int m0 = (q >> 1) * 128, n0 = (q & 1) * 128;
        const int nch = 8;

        int r0i = tid >> 2, seg0 = tid & 3;   // 128 rows x 4 segs

        auto load_stage = [&](int s, int ch) {
            int kb = ch * 32;
            uint32_t base = sb + s * STG_SZ;
            int gr = m0 + r0i; if (gr >= NN) gr = 0;
            const __nv_bfloat16* ah = g_A_hi + (size_t)gr * 512 + 256 + kb + seg0 * 8;
            const __nv_bfloat16* al = g_A_lo + (size_t)gr * 512 + 256 + kb + seg0 * 8;
            uint32_t d = base + r0i * 80 + seg0 * 16;
            cp16(d, ah);
            cp16(d + 10240, al);
            const __nv_bfloat16* bh = g_Bw_hi + bOff + (size_t)(n0 + r0i) * 512 + kb + seg0 * 8;
            const __nv_bfloat16* bl = g_Bw_lo + bOff + (size_t)(n0 + r0i) * 512 + kb + seg0 * 8;
            cp16(d + 20480, bh);
            cp16(d + 30720, bl);
        };

        float acc[2][4][4];
#pragma unroll
        for (int i = 0; i < 2; i++)
#pragma unroll
            for (int j = 0; j < 4; j++)
#pragma unroll
                for (int p = 0; p < 4; p++) acc[i][j][p] = 0.0f;

        load_stage(0, 0); CP_COMMIT();
        load_stage(1, 1); CP_COMMIT();

        int a_row = wm * 32 + (lane & 7) + ((lane >> 3) & 1) * 8;
        int a_colh = (lane >> 4) * 8;
        int b_row = wn * 32 + (lane & 7);
        int b_colh = ((lane >> 3) & 1) * 8;

        for (int ch = 0; ch < nch; ch++) {
            int st = ch % NSTG;
            CP_WAIT1();
            __syncthreads();
            if (ch + 2 < nch) load_stage((ch + 2) % NSTG, ch + 2);
            CP_COMMIT();
            uint32_t base = sb + st * STG_SZ;
#pragma unroll
            for (int k16 = 0; k16 < 2; k16++) {
                uint32_t ah[2][4], al[2][4], bh[4][2], bl[4][2];
#pragma unroll
                for (int mt = 0; mt < 2; mt++) {
                    uint32_t ad = base + (a_row + mt * 16) * 80 + (k16 * 16 + a_colh) * 2;
                    ldm_x4(ah[mt], ad);
                    ldm_x4(al[mt], ad + 10240);
                }
#pragma unroll
                for (int nt = 0; nt < 4; nt++) {
                    uint32_t bd = base + 20480 + (b_row + nt * 8) * 80 + (k16 * 16 + b_colh) * 2;
                    ldm_x2(bh[nt], bd);
                    ldm_x2(bl[nt], bd + 10240);
                }
#pragma unroll
                for (int mt = 0; mt < 2; mt++)
#pragma unroll
                    for (int nt = 0; nt < 4; nt++) {
                        mma16816(acc[mt][nt], ah[mt], bh[nt]);
                        mma16816(acc[mt][nt], al[mt], bh[nt]);
                        mma16816(acc[mt][nt], ah[mt], bl[nt]);
                    }
            }
        }
        int rbase = m0 + wm * 32 + (lane >> 2);
        int cbase = n0 + wn * 32 + (lane & 3) * 2;
#pragma unroll
        for (int mt = 0; mt < 2; mt++)
#pragma unroll
            for (int half = 0; half < 2; half++) {
                int row = rbase + mt * 16 + half * 8;
                if (row >= NN) continue;
#pragma unroll
                for (int nt = 0; nt < 4; nt++) {
                    int c = cbase + nt * 8;
                    *(float2*)(g_r + (size_t)row * 256 + c) =
                        make_float2(acc[mt][nt][half * 2], acc[mt][nt][half * 2 + 1]);
                }
            }
        return;
    }

    // ================= SpMM (16 warps, 16 nodes) =================
    int par = l & 1;
    if (b == 0 && tid == 0) { g_accA[par][0] = 0.0; g_accA[par][1] = 0.0; }
    int sid = q * 4 + rr;
    int node = sid * 16 + wrp;
    if (node >= NN) return;
    const float* __restrict__ h = (l == 0) ? g_x0 : g_h;

    float4 ca0, cb0, ca1, cb1;
    if (l == 0) {
        ca0 = ca1 = make_float4(1.f, 1.f, 1.f, 1.f);
        cb0 = cb1 = make_float4(0.f, 0.f, 0.f, 0.f);
    } else {
        int pp = (l - 1) & 1;
        double cnt = (double)NN * (double)D_HID;
        double mu = g_accA[pp][0] / cnt;
        double var = g_accA[pp][1] / cnt - mu * mu;
        if (var < 0.0) var = 0.0;
        float inv = (float)(1.0 / (sqrt(var) + 1e-5));
        float muf = (float)mu;
        int c0 = lane * 4, c1 = 128 + lane * 4;
        float4 g0 = *(const float4*)(gam + c0), g1 = *(const float4*)(gam + c1);
        float4 b0 = *(const float4*)(bet + c0), b1 = *(const float4*)(bet + c1);
        ca0 = make_float4(g0.x * inv, g0.y * inv, g0.z * inv, g0.w * inv);
        ca1 = make_float4(g1.x * inv, g1.y * inv, g1.z * inv, g1.w * inv);
        cb0 = make_float4(b0.x - muf * ca0.x, b0.y - muf * ca0.y, b0.z - muf * ca0.z, b0.w - muf * ca0.w);
        cb1 = make_float4(b1.x - muf * ca1.x, b1.y - muf * ca1.y, b1.z - muf * ca1.z, b1.w - muf * ca1.w);
    }

    int c = node;
    float dc = g_dis[c];
    float wself = dc * dc;
    const float4* hr = (const float4*)(h + (size_t)c * D_HID);
    float4 v0 = hr[lane], v1 = hr[lane + 32];
    float4 a0, a1;
    a0.x = wself * fmaxf(ca0.x * v0.x + cb0.x, 0.f);
    a0.y = wself * fmaxf(ca0.y * v0.y + cb0.y, 0.f);
    a0.z = wself * fmaxf(ca0.z * v0.z + cb0.z, 0.f);
    a0.w = wself * fmaxf(ca0.w * v0.w + cb0.w, 0.f);
    a1.x = wself * fmaxf(ca1.x * v1.x + cb1.x, 0.f);
    a1.y = wself * fmaxf(ca1.y * v1.y + cb1.y, 0.f);
    a1.z = wself * fmaxf(ca1.z * v1.z + cb1.z, 0.f);
    a1.w = wself * fmaxf(ca1.w * v1.w + cb1.w, 0.f);

    int beg = g_rowptr[c], end = g_rowptr[c + 1];
#pragma unroll 2
    for (int e = beg; e < end; e++) {
        int   s = __ldg(&g_src[e]);
        float w = __ldg(&g_w[e]);
        const float4* hs = (const float4*)(h + (size_t)s * D_HID);
        float4 b0 = __ldg(&hs[lane]);
        float4 b1 = __ldg(&hs[lane + 32]);
        a0.x += w * fmaxf(ca0.x * b0.x + cb0.x, 0.f);
        a0.y += w * fmaxf(ca0.y * b0.y + cb0.y, 0.f);
        a0.z += w * fmaxf(ca0.z * b0.z + cb0.z, 0.f);
        a0.w += w * fmaxf(ca0.w * b0.w + cb0.w, 0.f);
        a1.x += w * fmaxf(ca1.x * b1.x + cb1.x, 0.f);
        a1.y += w * fmaxf(ca1.y * b1.y + cb1.y, 0.f);
        a1.z += w * fmaxf(ca1.z * b1.z + cb1.z, 0.f);
        a1.w += w * fmaxf(ca1.w * b1.w + cb1.w, 0.f);
    }
    __nv_bfloat16* Ah = g_A_hi + (size_t)c * 512;
    __nv_bfloat16* Al = g_A_lo + (size_t)c * 512;
    float vv[8] = {0.5f * a0.x, 0.5f * a0.y, 0.5f * a0.z, 0.5f * a0.w,
                   0.5f * a1.x, 0.5f * a1.y, 0.5f * a1.z, 0.5f * a1.w};
    int cols[2] = {lane * 4, 128 + lane * 4};
#pragma unroll
    for (int g = 0; g < 2; g++) {
        __nv_bfloat16 h4[4], l4[4];
#pragma unroll
        for (int j = 0; j < 4; j++) split2(vv[g * 4 + j], h4[j], l4[j]);
        *(__nv_bfloat162*)(Ah + cols[g])     = __nv_bfloat162(h4[0], h4[1]);
        *(__nv_bfloat162*)(Ah + cols[g] + 2) = __nv_bfloat162(h4[2], h4[3]);
        *(__nv_bfloat162*)(Al + cols[g])     = __nv_bfloat162(l4[0], l4[1]);
        *(__nv_bfloat162*)(Al + cols[g] + 2) = __nv_bfloat162(l4[2], l4[3]);
    }
}

// ------------------------- mma.sync GEMM (8 warps) -------------------------
// mode 1: lin1  A=xin (lda=128), K=128 : relu(acc+bias)->g_x0 + 0.5x0 splits
// mode 2: GEMM_t A=g_A (lda=512), K=256 : acc + g_r -> g_h + global sums
// mode 3: lin2  A=g_A (lda=512), K=256 : relu(acc+bias)->Cout
__global__ void __launch_bounds__(256) k_mma(int mode, int bOff, int K, int ldb, int N,
                                             const float* __restrict__ bias,
                                             float* __restrict__ Cout, int parity) {
    extern __shared__ char smem[];
    uint32_t sb = smem_u32(smem);
    int tid = threadIdx.x;
    int lane = tid & 31, wrp = tid >> 5;
    int wm = wrp & 1, wn = wrp >> 1;
    int m0 = blockIdx.y * 128, n0 = blockIdx.x * 128;

    const __nv_bfloat16* Ahi = (mode == 1) ? g_xin_hi : g_A_hi;
    const __nv_bfloat16* Alo = (mode == 1) ? g_xin_lo : g_A_lo;
    const int lda = (mode == 1) ? 128 : 512;
    const __nv_bfloat16* Bhi = g_Bw_hi + bOff;
    const __nv_bfloat16* Blo = g_Bw_lo + bOff;

    const int nch = K / 32;

    int r0i = tid >> 2, seg0 = (tid & 3);
    int r1i = (tid + 256) >> 2;

    auto load_stage = [&](int s, int ch) {
        int kb = ch * 32;
        uint32_t base = sb + s * STG_SZ;
        int gr0 = m0 + r0i; if (gr0 >= NN) gr0 = 0;
        int gr1 = m0 + r1i; if (gr1 >= NN) gr1 = 0;
        const __nv_bfloat16* a0h = Ahi + (size_t)gr0 * lda + kb + seg0 * 8;
        const __nv_bfloat16* a1h = Ahi + (size_t)gr1 * lda + kb + seg0 * 8;
        const __nv_bfloat16* a0l = Alo + (size_t)gr0 * lda + kb + seg0 * 8;
        const __nv_bfloat16* a1l = Alo + (size_t)gr1 * lda + kb + seg0 * 8;
        uint32_t d0 = base + r0i * 80 + seg0 * 16;
        uint32_t d1 = base + r1i * 80 + seg0 * 16;
        cp16(d0, a0h);          cp16(d1, a1h);
        cp16(d0 + 10240, a0l);  cp16(d1 + 10240, a1l);
        const __nv_bfloat16* b0h = Bhi + (size_t)(n0 + r0i) * ldb + kb + seg0 * 8;
        const __nv_bfloat16* b1h = Bhi + (size_t)(n0 + r1i) * ldb + kb + seg0 * 8;
        const __nv_bfloat16* b0l = Blo + (size_t)(n0 + r0i) * ldb + kb + seg0 * 8;
        const __nv_bfloat16* b1l = Blo + (size_t)(n0 + r1i) * ldb + kb + seg0 * 8;
        cp16(d0 + 20480, b0h);  cp16(d1 + 20480, b1h);
        cp16(d0 + 30720, b0l);  cp16(d1 + 30720, b1l);
    };

    float acc[4][4][4];
#pragma unroll
    for (int i = 0; i < 4; i++)
#pragma unroll
        for (int j = 0; j < 4; j++)
#pragma unroll
            for (int p = 0; p < 4; p++) acc[i][j][p] = 0.0f;

    load_stage(0, 0); CP_COMMIT();
    load_stage(1, 1); CP_COMMIT();

    int a_row = wm * 64 + (lane & 7) + ((lane >> 3) & 1) * 8;
    int a_colh = (lane >> 4) * 8;
    int b_row = wn * 32 + (lane & 7);
    int b_colh = ((lane >> 3) & 1) * 8;

    for (int ch = 0; ch < nch; ch++) {
        int st = ch % NSTG;
        CP_WAIT1();
        __syncthreads();
        if (ch + 2 < nch) load_stage((ch + 2) % NSTG, ch + 2);
        CP_COMMIT();
        uint32_t base = sb + st * STG_SZ;
#pragma unroll
        for (int k16 = 0; k16 < 2; k16++) {
            uint32_t ah[4][4], al[4][4], bh[4][2], bl[4][2];
#pragma unroll
            for (int mt = 0; mt < 4; mt++) {
                uint32_t ad = base + (a_row + mt * 16) * 80 + (k16 * 16 + a_colh) * 2;
                ldm_x4(ah[mt], ad);
                ldm_x4(al[mt], ad + 10240);
            }
#pragma unroll
            for (int nt = 0; nt < 4; nt++) {
                uint32_t bd = base + 20480 + (b_row + nt * 8) * 80 + (k16 * 16 + b_colh) * 2;
                ldm_x2(bh[nt], bd);
                ldm_x2(bl[nt], bd + 10240);
            }
#pragma unroll
            for (int mt = 0; mt < 4; mt++)
#pragma unroll
                for (int nt = 0; nt < 4; nt++) {
                    mma16816(acc[mt][nt], ah[mt], bh[nt]);
                    mma16816(acc[mt][nt], al[mt], bh[nt]);
                    mma16816(acc[mt][nt], ah[mt], bl[nt]);
                }
        }
    }

    // ------------- epilogue -------------
    float sum = 0.0f, ssum = 0.0f;
    int rbase = m0 + wm * 64 + (lane >> 2);
    int cbase = n0 + wn * 32 + (lane & 3) * 2;
#pragma unroll
    for (int mt = 0; mt < 4; mt++) {
#pragma unroll
        for (int half = 0; half < 2; half++) {
            int row = rbase + mt * 16 + half * 8;
            if (row >= NN) continue;
#pragma unroll
            for (int nt = 0; nt < 4; nt++) {
                int c = cbase + nt * 8;
                float v0 = acc[mt][nt][half * 2 + 0];
                float v1 = acc[mt][nt][half * 2 + 1];
                if (mode == 2) {
                    size_t idx = (size_t)row * 256 + c;
                    float2 rv = *(const float2*)(g_r + idx);
                    v0 += rv.x; v1 += rv.y;
                    *(float2*)(g_h + idx) = make_float2(v0, v1);
                    sum += v0 + v1;
                    ssum += v0 * v0 + v1 * v1;
                } else if (mode == 1) {
                    float r0 = fmaxf(v0 + __ldg(&bias[c]), 0.0f);
                    float r1 = fmaxf(v1 + __ldg(&bias[c + 1]), 0.0f);
                    *(float2*)(g_x0 + (size_t)row * 256 + c) = make_float2(r0, r1);
                    __nv_bfloat16 h0, l0, h1, l1;
                    split2(0.5f * r0, h0, l0);
                    split2(0.5f * r1, h1, l1);
                    size_t sidx = (size_t)row * 512 + 256 + c;
                    *(__nv_bfloat162*)(g_A_hi + sidx) = __nv_bfloat162(h0, h1);
                    *(__nv_bfloat162*)(g_A_lo + sidx) = __nv_bfloat162(l0, l1);
                } else {
                    float r0 = fmaxf(v0 + __ldg(&bias[c]), 0.0f);
                    float r1 = fmaxf(v1 + __ldg(&bias[c + 1]), 0.0f);
                    *(float2*)(Cout + (size_t)row * N + c) = make_float2(r0, r1);
                }
            }
        }
    }
    if (mode == 2) {
#pragma unroll
        for (int off = 16; off > 0; off >>= 1) {
            sum  += __shfl_down_sync(0xffffffffu, sum, off);
            ssum += __shfl_down_sync(0xffffffffu, ssum, off);
        }
        __syncthreads();
        float* rs  = (float*)smem;
        float* rss = (float*)smem + 32;
        if (lane == 0) { rs[wrp] = sum; rss[wrp] = ssum; }
        __syncthreads();
        if (tid == 0) {
            float S = 0.f, SS = 0.f;
            for (int w = 0; w < 8; w++) { S += rs[w]; SS += rss[w]; }
            atomicAdd(&g_accA[parity][0], (double)S);
            atomicAdd(&g_accA[parity][1], (double)SS);
        }
    }
}

// ------------------------- final norm -> lin2 input splits ---------------
__global__ void k_norm_final(const float* __restrict__ gam, const float* __restrict__ bet) {
    double cnt = (double)NN * (double)D_HID;
    double mu = g_accA[1][0] / cnt;
    double var = g_accA[1][1] / cnt - mu * mu;
    if (var < 0.0) var = 0.0;
    float inv = (float)(1.0 / (sqrt(var) + 1e-5));
    float muf = (float)mu;
    size_t total = (size_t)NN * D_HID / 4;
    size_t i = (size_t)blockIdx.x * blockDim.x + threadIdx.x;
    if (i >= total) return;
    float4 v = ((const float4*)g_h)[i];
    int c = (int)((i * 4) & (D_HID - 1));
    float4 gg = *(const float4*)(gam + c);
    float4 bb = *(const float4*)(bet + c);
    float r0 = fmaxf(gg.x * ((v.x - muf) * inv) + bb.x, 0.0f);
    float r1 = fmaxf(gg.y * ((v.y - muf) * inv) + bb.y, 0.0f);
    float r2 = fmaxf(gg.z * ((v.z - muf) * inv) + bb.z, 0.0f);
    float r3 = fmaxf(gg.w * ((v.w - muf) * inv) + bb.w, 0.0f);
    size_t row = (i * 4) >> 8;
    size_t base = row * 512 + c;
    __nv_bfloat16 h4[4], l4[4];
    split2(r0, h4[0], l4[0]); split2(r1, h4[1], l4[1]);
    split2(r2, h4[2], l4[2]); split2(r3, h4[3], l4[3]);
    *(__nv_bfloat162*)(g_A_hi + base)     = __nv_bfloat162(h4[0], h4[1]);
    *(__nv_bfloat162*)(g_A_hi + base + 2) = __nv_bfloat162(h4[2], h4[3]);
    *(__nv_bfloat162*)(g_A_lo + base)     = __nv_bfloat162(l4[0], l4[1]);
    *(__nv_bfloat162*)(g_A_lo + base + 2) = __nv_bfloat162(l4[2], l4[3]);
}

// ------------------------- launch -------------------------
extern "C" void kernel_launch(void* const* d_in, const int* in_sizes, int n_in,
                              void* d_out, int out_size) {
    const float* x       = (const float*)d_in[0];
    const int*   ei      = (const int*)  d_in[1];
    const float* lin1_w  = (const float*)d_in[2];
    const float* lin1_b  = (const float*)d_in[3];
    const float* conv_w1 = (const float*)d_in[4];
    const float* conv_w2 = (const float*)d_in[5];
    const float* gamma   = (const float*)d_in[6];
    const float* betaa   = (const float*)d_in[7];
    const float* lin2_w  = (const float*)d_in[8];
    const float* lin2_b  = (const float*)d_in[9];
    float* out = (float*)d_out;

    static int smem_set = 0;
    if (!smem_set) {
        cudaFuncSetAttribute(k_mma, cudaFuncAttributeMaxDynamicSharedMemorySize, SM_TOTAL);
        cudaFuncSetAttribute(k_mix, cudaFuncAttributeMaxDynamicSharedMemorySize, SM_TOTAL);
        smem_set = 1;
    }

    // graph normalization + CSR build
    k_init<<<(NN + 255) / 256, 256>>>();
    k_edge_count<<<(NE + 255) / 256, 256>>>(ei);
    k_rsqrt<<<(NN + 255) / 256, 256>>>();
    k_scan_part<<<49, 1024>>>();
    k_scan_top<<<1, 32>>>();
    k_scan_out<<<49, 1024>>>();
    k_cursor<<<(NN + 255) / 256, 256>>>();
    k_scatter<<<(NE + 255) / 256, 256>>>(ei);

    // bf16 operand prep
    k_prep_w<<<(WB_TOT + 255) / 256, 256>>>(lin1_w, conv_w1, conv_w2, lin2_w);
    k_prep_x<<<(NN * D_IN + 255) / 256, 256>>>(x);

    const int MT = (NN + 127) / 128;  // 391

    // lin1 + relu -> g_x0 (+ 0.5*x0 splits)
    k_mma<<<dim3(2, MT), 256, SM_TOTAL>>>(1, WB_L1, 128, 128, 256, lin1_b, nullptr, 0);

    // 8 GCNII layers: [SpMM || GEMM_r] then GEMM_t
    for (int l = 0; l < NL; l++) {
        k_mix<<<3912, 512, SM_TOTAL>>>(l, gamma + (size_t)(l > 0 ? l - 1 : 0) * D_HID,
                                       betaa + (size_t)(l > 0 ? l - 1 : 0) * D_HID,
                                       WB_LYR + l * 131072 + 256);
        k_mma<<<dim3(2, MT), 256, SM_TOTAL>>>(2, WB_LYR + l * 131072, 256, 512, 256,
                                              nullptr, nullptr, l & 1);
    }

    // final norm (layer 7 params) -> lin2 input splits
    k_norm_final<<<(NN * D_HID / 4 + 255) / 256, 256>>>(gamma + 7 * (size_t)D_HID,
                                                        betaa + 7 * (size_t)D_HID);

    // lin2 + relu -> out
    k_mma<<<dim3(1, MT), 256, SM_TOTAL>>>(3, WB_L2, 256, 256, 128, lin2_b, out, 0);

    (void)in_sizes; (void)n_in; (void)out_size;
}

// round 6
// speedup vs baseline: 1.3618x; 1.3618x over previous
#include <cuda_runtime.h>
#include <cuda_bf16.h>
#include <math.h>
#include <stdint.h>

#define NN   50000
#define NE   800000
#define D_IN 128
#define D_HID 256
#define D_OUT 128
#define NL   8

// ---------------- weight buffer layout (transposed, K-major [N][K]) ------
#define WB_L1   0                         // lin1: [256][128]
#define WB_LYR  32768                     // layers: 8 x [256][512]  (W' = beta*W + omb*I)
#define WB_L2   (32768 + 8 * 131072)      // lin2: [128][256]
#define WB_TOT  (WB_L2 + 32768)

// ------------------------- static device scratch -------------------------
__device__ float  g_dis[NN];
__device__ int    g_rowptr[NN + 1];
__device__ int    g_cnt[NN];
__device__ int    g_bsum[64];
__device__ int    g_boff[64];
__device__ int    g_src[NE];
__device__ float  g_w[NE];
__device__ float  g_x0[(size_t)NN * D_HID];
__device__ float  g_h [(size_t)NN * D_HID];
__device__ float  g_r8[(size_t)NL * NN * D_HID];      // per-layer r@W2'
__device__ double g_accA[2][2];           // [parity][sum, sumsq]
// bf16 split operands
__device__ __nv_bfloat16 g_A_hi[(size_t)NN * 512];   // cols 0..255: t ; 256..511: 0.5*x0 (or h_norm)
__device__ __nv_bfloat16 g_A_lo[(size_t)NN * 512];
__device__ __nv_bfloat16 g_xin_hi[(size_t)NN * D_IN];
__device__ __nv_bfloat16 g_xin_lo[(size_t)NN * D_IN];
__device__ __nv_bfloat16 g_Bw_hi[WB_TOT];
__device__ __nv_bfloat16 g_Bw_lo[WB_TOT];

// ------------------------- helpers -------------------------
__device__ __forceinline__ uint32_t smem_u32(const void* p) {
    uint32_t a;
    asm("{ .reg .u64 t; cvta.to.shared.u64 t, %1; cvt.u32.u64 %0, t; }" : "=r"(a) : "l"(p));
    return a;
}
__device__ __forceinline__ void cp16(uint32_t dst, const void* src) {
    asm volatile("cp.async.cg.shared.global [%0], [%1], 16;" :: "r"(dst), "l"(src));
}
#define CP_COMMIT() asm volatile("cp.async.commit_group;" ::: "memory")
#define CP_WAIT1()  asm volatile("cp.async.wait_group 1;" ::: "memory")

__device__ __forceinline__ void ldm_x4(uint32_t* r, uint32_t addr) {
    asm volatile("ldmatrix.sync.aligned.m8n8.x4.shared.b16 {%0,%1,%2,%3}, [%4];"
                 : "=r"(r[0]), "=r"(r[1]), "=r"(r[2]), "=r"(r[3]) : "r"(addr));
}
__device__ __forceinline__ void ldm_x2(uint32_t* r, uint32_t addr) {
    asm volatile("ldmatrix.sync.aligned.m8n8.x2.shared.b16 {%0,%1}, [%2];"
                 : "=r"(r[0]), "=r"(r[1]) : "r"(addr));
}
__device__ __forceinline__ void mma16816(float* c, const uint32_t* a, const uint32_t* b) {
    asm volatile("mma.sync.aligned.m16n8k16.row.col.f32.bf16.bf16.f32 "
                 "{%0,%1,%2,%3}, {%4,%5,%6,%7}, {%8,%9}, {%0,%1,%2,%3};"
                 : "+f"(c[0]), "+f"(c[1]), "+f"(c[2]), "+f"(c[3])
                 : "r"(a[0]), "r"(a[1]), "r"(a[2]), "r"(a[3]), "r"(b[0]), "r"(b[1]));
}
__device__ __forceinline__ void split2(float v, __nv_bfloat16& h, __nv_bfloat16& l) {
    h = __float2bfloat16(v);
    l = __float2bfloat16(v - __bfloat162float(h));
}

// ------------------------- setup kernels -------------------------
__global__ void k_init() {
    int i = blockIdx.x * blockDim.x + threadIdx.x;
    if (i < NN) { g_dis[i] = 1.0f; g_cnt[i] = 0; }
}
__global__ void k_edge_count(const int* __restrict__ ei) {
    int e = blockIdx.x * blockDim.x + threadIdx.x;
    if (e < NE) {
        int c = ei[NE + e];
        atomicAdd(&g_dis[c], 1.0f);
        atomicAdd(&g_cnt[c], 1);
    }
}
__global__ void k_rsqrt() {
    int i = blockIdx.x * blockDim.x + threadIdx.x;
    if (i < NN) g_dis[i] = rsqrtf(g_dis[i]);
}
__device__ __forceinline__ int block_scan_inc(int v, int* wsum) {
    int lane = threadIdx.x & 31, wid = threadIdx.x >> 5;
#pragma unroll
    for (int o = 1; o < 32; o <<= 1) { int t = __shfl_up_sync(~0u, v, o); if (lane >= o) v += t; }
    if (lane == 31) wsum[wid] = v;
    __syncthreads();
    if (wid == 0) {
        int w = wsum[lane];
#pragma unroll
        for (int o = 1; o < 32; o <<= 1) { int t = __shfl_up_sync(~0u, w, o); if (lane >= o) w += t; }
        wsum[lane] = w;
    }
    __syncthreads();
    return v + (wid > 0 ? wsum[wid - 1] : 0);
}
__global__ void k_scan_part() {
    __shared__ int wsum[32];
    int i = blockIdx.x * 1024 + threadIdx.x;
    int v = (i < NN) ? g_cnt[i] : 0;
    int inc = block_scan_inc(v, wsum);
    if (threadIdx.x == 1023) g_bsum[blockIdx.x] = inc;
}
__global__ void k_scan_top() {
    if (threadIdx.x == 0) {
        int run = 0;
        for (int b = 0; b < 49; b++) { g_boff[b] = run; run += g_bsum[b]; }
        g_rowptr[NN] = run;
    }
}
__global__ void k_scan_out() {
    __shared__ int wsum[32];
    int i = blockIdx.x * 1024 + threadIdx.x;
    int v = (i < NN) ? g_cnt[i] : 0;
    int inc = block_scan_inc(v, wsum);
    if (i < NN) g_rowptr[i] = g_boff[blockIdx.x] + inc - v;   // exclusive
}
__global__ void k_cursor() {
    int i = blockIdx.x * blockDim.x + threadIdx.x;
    if (i < NN) g_cnt[i] = g_rowptr[i];
}
__global__ void k_scatter(const int* __restrict__ ei) {
    int e = blockIdx.x * blockDim.x + threadIdx.x;
    if (e < NE) {
        int r = ei[e];
        int c = ei[NE + e];
        int s = atomicAdd(&g_cnt[c], 1);
        g_src[s] = r;
        g_w[s]   = g_dis[r] * g_dis[c];
    }
}

// ------------------------- weight / input prep (bf16 splits) -------------
__global__ void k_prep_w(const float* __restrict__ lin1_w, const float* __restrict__ w1,
                         const float* __restrict__ w2, const float* __restrict__ lin2_w) {
    int idx = blockIdx.x * blockDim.x + threadIdx.x;
    if (idx >= WB_TOT) return;
    float v;
    if (idx < WB_LYR) {                       // lin1: [n=256][k=128]
        int n = idx >> 7, k = idx & 127;
        v = lin1_w[k * 256 + n];
    } else if (idx < WB_L2) {                 // layer l: [n=256][k=512]
        int r = idx - WB_LYR;
        int l = r >> 17;
        int q = r & 131071;
        int n = q >> 9, k = q & 511;
        float beta = logf((float)(l + 2) / (float)(l + 1));
        float omb = 1.0f - beta;
        if (k < 256) v = beta * w1[l * 65536 + k * 256 + n] + ((k == n) ? omb : 0.0f);
        else {
            int k2 = k - 256;
            v = beta * w2[l * 65536 + k2 * 256 + n] + ((k2 == n) ? omb : 0.0f);
        }
    } else {                                  // lin2: [n=128][k=256]
        int r = idx - WB_L2;
        int n = r >> 8, k = r & 255;
        v = lin2_w[k * 128 + n];
    }
    __nv_bfloat16 h, l;
    split2(v, h, l);
    g_Bw_hi[idx] = h;
    g_Bw_lo[idx] = l;
}
__global__ void k_prep_x(const float* __restrict__ x) {
    size_t idx = (size_t)blockIdx.x * blockDim.x + threadIdx.x;
    if (idx >= (size_t)NN * D_IN) return;
    __nv_bfloat16 h, l;
    split2(x[idx], h, l);
    g_xin_hi[idx] = h;
    g_xin_lo[idx] = l;
}

// ------------------------- SpMM with fused norm+relu on gather -----------
__global__ void __launch_bounds__(256) k_spmm(int l, const float* __restrict__ gam,
                                              const float* __restrict__ bet) {
    int par = l & 1;
    if (blockIdx.x == 0 && threadIdx.x == 0) { g_accA[par][0] = 0.0; g_accA[par][1] = 0.0; }
    int warp = (blockIdx.x * blockDim.x + threadIdx.x) >> 5;
    int lane = threadIdx.x & 31;
    if (warp >= NN) return;
    const float* __restrict__ h = (l == 0) ? g_x0 : g_h;

    float4 ca0, cb0, ca1, cb1;
    if (l == 0) {
        ca0 = ca1 = make_float4(1.f, 1.f, 1.f, 1.f);
        cb0 = cb1 = make_float4(0.f, 0.f, 0.f, 0.f);
    } else {
        int pp = (l - 1) & 1;
        double cnt = (double)NN * (double)D_HID;
        double mu = g_accA[pp][0] / cnt;
        double var = g_accA[pp][1] / cnt - mu * mu;
        if (var < 0.0) var = 0.0;
        float inv = (float)(1.0 / (sqrt(var) + 1e-5));
        float muf = (float)mu;
        int c0 = lane * 4, c1 = 128 + lane * 4;
        float4 g0 = *(const float4*)(gam + c0), g1 = *(const float4*)(gam + c1);
        float4 b0 = *(const float4*)(bet + c0), b1 = *(const float4*)(bet + c1);
        ca0 = make_float4(g0.x * inv, g0.y * inv, g0.z * inv, g0.w * inv);
        ca1 = make_float4(g1.x * inv, g1.y * inv, g1.z * inv, g1.w * inv);
        cb0 = make_float4(b0.x - muf * ca0.x, b0.y - muf * ca0.y, b0.z - muf * ca0.z, b0.w - muf * ca0.w);
        cb1 = make_float4(b1.x - muf * ca1.x, b1.y - muf * ca1.y, b1.z - muf * ca1.z, b1.w - muf * ca1.w);
    }

    int c = warp;
    float dc = g_dis[c];
    float wself = dc * dc;
    const float4* hr = (const float4*)(h + (size_t)c * D_HID);
    float4 v0 = hr[lane], v1 = hr[lane + 32];
    float4 a0, a1;
    a0.x = wself * fmaxf(ca0.x * v0.x + cb0.x, 0.f);
    a0.y = wself * fmaxf(ca0.y * v0.y + cb0.y, 0.f);
    a0.z = wself * fmaxf(ca0.z * v0.z + cb0.z, 0.f);
    a0.w = wself * fmaxf(ca0.w * v0.w + cb0.w, 0.f);
    a1.x = wself * fmaxf(ca1.x * v1.x + cb1.x, 0.f);
    a1.y = wself * fmaxf(ca1.y * v1.y + cb1.y, 0.f);
    a1.z = wself * fmaxf(ca1.z * v1.z + cb1.z, 0.f);
    a1.w = wself * fmaxf(ca1.w * v1.w + cb1.w, 0.f);

    int beg = g_rowptr[c], end = g_rowptr[c + 1];
#pragma unroll 2
    for (int e = beg; e < end; e++) {
        int   s = __ldg(&g_src[e]);
        float w = __ldg(&g_w[e]);
        const float4* hs = (const float4*)(h + (size_t)s * D_HID);
        float4 b0 = __ldg(&hs[lane]);
        float4 b1 = __ldg(&hs[lane + 32]);
        a0.x += w * fmaxf(ca0.x * b0.x + cb0.x, 0.f);
        a0.y += w * fmaxf(ca0.y * b0.y + cb0.y, 0.f);
        a0.z += w * fmaxf(ca0.z * b0.z + cb0.z, 0.f);
        a0.w += w * fmaxf(ca0.w * b0.w + cb0.w, 0.f);
        a1.x += w * fmaxf(ca1.x * b1.x + cb1.x, 0.f);
        a1.y += w * fmaxf(ca1.y * b1.y + cb1.y, 0.f);
        a1.z += w * fmaxf(ca1.z * b1.z + cb1.z, 0.f);
        a1.w += w * fmaxf(ca1.w * b1.w + cb1.w, 0.f);
    }
    __nv_bfloat16* Ah = g_A_hi + (size_t)c * 512;
    __nv_bfloat16* Al = g_A_lo + (size_t)c * 512;
    float vv[8] = {0.5f * a0.x, 0.5f * a0.y, 0.5f * a0.z, 0.5f * a0.w,
                   0.5f * a1.x, 0.5f * a1.y, 0.5f * a1.z, 0.5f * a1.w};
    int cols[2] = {lane * 4, 128 + lane * 4};
#pragma unroll
    for (int g = 0; g < 2; g++) {
        __nv_bfloat16 h4[4], l4[4];
#pragma unroll
        for (int j = 0; j < 4; j++) split2(vv[g * 4 + j], h4[j], l4[j]);
        *(__nv_bfloat162*)(Ah + cols[g])     = __nv_bfloat162(h4[0], h4[1]);
        *(__nv_bfloat162*)(Ah + cols[g] + 2) = __nv_bfloat162(h4[2], h4[3]);
        *(__nv_bfloat162*)(Al + cols[g])     = __nv_bfloat162(l4[0], l4[1]);
        *(__nv_bfloat162*)(Al + cols[g] + 2) = __nv_bfloat162(l4[2], l4[3]);
    }
}

// ------------------------- mma.sync GEMM (8 warps, 3-stage) --------------
// mode 0: GEMM_r A=g_A cols 256..511, K=256 : acc -> g_r8[layer]
// mode 1: lin1   A=xin (lda=128), K=128    : relu(acc+bias)->g_x0 + 0.5x0 splits
// mode 2: GEMM_t A=g_A cols 0..255, K=256  : acc + g_r8[layer] -> g_h + sums
// mode 3: lin2   A=g_A (lda=512), K=256    : relu(acc+bias)->Cout
#define STG_SZ 40960
#define NSTG 3
#define SM_TOTAL (NSTG * STG_SZ)

__global__ void __launch_bounds__(256) k_mma(int mode, int bOff, int K, int ldb, int N,
                                             const float* __restrict__ bias,
                                             float* __restrict__ Cout, int layer) {
    extern __shared__ char smem[];
    uint32_t sb = smem_u32(smem);
    int tid = threadIdx.x;
    int lane = tid & 31, wrp = tid >> 5;
    int wm = wrp & 1, wn = wrp >> 1;
    int m0 = blockIdx.y * 128, n0 = blockIdx.x * 128;

    const __nv_bfloat16* Ahi = (mode == 1) ? g_xin_hi : ((mode == 0) ? g_A_hi + 256 : g_A_hi);
    const __nv_bfloat16* Alo = (mode == 1) ? g_xin_lo : ((mode == 0) ? g_A_lo + 256 : g_A_lo);
    const int lda = (mode == 1) ? 128 : 512;
    const __nv_bfloat16* Bhi = g_Bw_hi + bOff;
    const __nv_bfloat16* Blo = g_Bw_lo + bOff;

    const int nch = K / 32;

    int r0i = tid >> 2, seg0 = (tid & 3);
    int r1i = (tid + 256) >> 2;

    auto load_stage = [&](int s, int ch) {
        int kb = ch * 32;
        uint32_t base = sb + s * STG_SZ;
        int gr0 = m0 + r0i; if (gr0 >= NN) gr0 = 0;
        int gr1 = m0 + r1i; if (gr1 >= NN) gr1 = 0;
        const __nv_bfloat16* a0h = Ahi + (size_t)gr0 * lda + kb + seg0 * 8;
        const __nv_bfloat16* a1h = Ahi + (size_t)gr1 * lda + kb + seg0 * 8;
        const __nv_bfloat16* a0l = Alo + (size_t)gr0 * lda + kb + seg0 * 8;
        const __nv_bfloat16* a1l = Alo + (size_t)gr1 * lda + kb + seg0 * 8;
        uint32_t d0 = base + r0i * 80 + seg0 * 16;
        uint32_t d1 = base + r1i * 80 + seg0 * 16;
        cp16(d0, a0h);          cp16(d1, a1h);
        cp16(d0 + 10240, a0l);  cp16(d1 + 10240, a1l);
        const __nv_bfloat16* b0h = Bhi + (size_t)(n0 + r0i) * ldb + kb + seg0 * 8;
        const __nv_bfloat16* b1h = Bhi + (size_t)(n0 + r1i) * ldb + kb + seg0 * 8;
        const __nv_bfloat16* b0l = Blo + (size_t)(n0 + r0i) * ldb + kb + seg0 * 8;
        const __nv_bfloat16* b1l = Blo + (size_t)(n0 + r1i) * ldb + kb + seg0 * 8;
        cp16(d0 + 20480, b0h);  cp16(d1 + 20480, b1h);
        cp16(d0 + 30720, b0l);  cp16(d1 + 30720, b1l);
    };

    float acc[4][4][4];
#pragma unroll
    for (int i = 0; i < 4; i++)
#pragma unroll
        for (int j = 0; j < 4; j++)
#pragma unroll
            for (int p = 0; p < 4; p++) acc[i][j][p] = 0.0f;

    load_stage(0, 0); CP_COMMIT();
    load_stage(1, 1); CP_COMMIT();

    int a_row = wm * 64 + (lane & 7) + ((lane >> 3) & 1) * 8;
    int a_colh = (lane >> 4) * 8;
    int b_row = wn * 32 + (lane & 7);
    int b_colh = ((lane >> 3) & 1) * 8;

    for (int ch = 0; ch < nch; ch++) {
        int st = ch % NSTG;
        CP_WAIT1();
        __syncthreads();
        if (ch + 2 < nch) load_stage((ch + 2) % NSTG, ch + 2);
        CP_COMMIT();
        uint32_t base = sb + st * STG_SZ;
#pragma unroll
        for (int k16 = 0; k16 < 2; k16++) {
            uint32_t ah[4][4], al[4][4], bh[4][2], bl[4][2];
#pragma unroll
            for (int mt = 0; mt < 4; mt++) {
                uint32_t ad = base + (a_row + mt * 16) * 80 + (k16 * 16 + a_colh) * 2;
                ldm_x4(ah[mt], ad);
                ldm_x4(al[mt], ad + 10240);
            }
#pragma unroll
            for (int nt = 0; nt < 4; nt++) {
                uint32_t bd = base + 20480 + (b_row + nt * 8) * 80 + (k16 * 16 + b_colh) * 2;
                ldm_x2(bh[nt], bd);
                ldm_x2(bl[nt], bd + 10240);
            }
#pragma unroll
            for (int mt = 0; mt < 4; mt++)
#pragma unroll
                for (int nt = 0; nt < 4; nt++) {
                    mma16816(acc[mt][nt], ah[mt], bh[nt]);
                    mma16816(acc[mt][nt], al[mt], bh[nt]);
                    mma16816(acc[mt][nt], ah[mt], bl[nt]);
                }
        }
    }

    // ------------- epilogue -------------
    float sum = 0.0f, ssum = 0.0f;
    float* rbuf = g_r8 + (size_t)layer * NN * D_HID;
    int rbase = m0 + wm * 64 + (lane >> 2);
    int cbase = n0 + wn * 32 + (lane & 3) * 2;
#pragma unroll
    for (int mt = 0; mt < 4; mt++) {
#pragma unroll
        for (int half = 0; half < 2; half++) {
            int row = rbase + mt * 16 + half * 8;
            if (row >= NN) continue;
#pragma unroll
            for (int nt = 0; nt < 4; nt++) {
                int c = cbase + nt * 8;
                float v0 = acc[mt][nt][half * 2 + 0];
                float v1 = acc[mt][nt][half * 2 + 1];
                if (mode == 2) {
                    size_t idx = (size_t)row * 256 + c;
                    float2 rv = *(const float2*)(rbuf + idx);
                    v0 += rv.x; v1 += rv.y;
                    *(float2*)(g_h + idx) = make_float2(v0, v1);
                    sum += v0 + v1;
                    ssum += v0 * v0 + v1 * v1;
                } else if (mode == 0) {
                    *(float2*)(rbuf + (size_t)row * 256 + c) = make_float2(v0, v1);
                } else if (mode == 1) {
                    float r0 = fmaxf(v0 + __ldg(&bias[c]), 0.0f);
                    float r1 = fmaxf(v1 + __ldg(&bias[c + 1]), 0.0f);
                    *(float2*)(g_x0 + (size_t)row * 256 + c) = make_float2(r0, r1);
                    __nv_bfloat16 h0, l0, h1, l1;
                    split2(0.5f * r0, h0, l0);
                    split2(0.5f * r1, h1, l1);
                    size_t sidx = (size_t)row * 512 + 256 + c;
                    *(__nv_bfloat162*)(g_A_hi + sidx) = __nv_bfloat162(h0, h1);
                    *(__nv_bfloat162*)(g_A_lo + sidx) = __nv_bfloat162(l0, l1);
                } else {
                    float r0 = fmaxf(v0 + __ldg(&bias[c]), 0.0f);
                    float r1 = fmaxf(v1 + __ldg(&bias[c + 1]), 0.0f);
                    *(float2*)(Cout + (size_t)row * N + c) = make_float2(r0, r1);
                }
            }
        }
    }
    if (mode == 2) {
#pragma unroll
        for (int off = 16; off > 0; off >>= 1) {
            sum  += __shfl_down_sync(0xffffffffu, sum, off);
            ssum += __shfl_down_sync(0xffffffffu, ssum, off);
        }
        __syncthreads();
        float* rs  = (float*)smem;
        float* rss = (float*)smem + 32;
        if (lane == 0) { rs[wrp] = sum; rss[wrp] = ssum; }
        __syncthreads();
        if (tid == 0) {
            float S = 0.f, SS = 0.f;
            for (int w = 0; w < 8; w++) { S += rs[w]; SS += rss[w]; }
            atomicAdd(&g_accA[layer & 1][0], (double)S);
            atomicAdd(&g_accA[layer & 1][1], (double)SS);
        }
    }
}

// ------------------------- final norm -> lin2 input splits ---------------
__global__ void k_norm_final(const float* __restrict__ gam, const float* __restrict__ bet) {
    double cnt = (double)NN * (double)D_HID;
    double mu = g_accA[1][0] / cnt;
    double var = g_accA[1][1] / cnt - mu * mu;
    if (var < 0.0) var = 0.0;
    float inv = (float)(1.0 / (sqrt(var) + 1e-5));
    float muf = (float)mu;
    size_t total = (size_t)NN * D_HID / 4;
    size_t i = (size_t)blockIdx.x * blockDim.x + threadIdx.x;
    if (i >= total) return;
    float4 v = ((const float4*)g_h)[i];
    int c = (int)((i * 4) & (D_HID - 1));
    float4 gg = *(const float4*)(gam + c);
    float4 bb = *(const float4*)(bet + c);
    float r0 = fmaxf(gg.x * ((v.x - muf) * inv) + bb.x, 0.0f);
    float r1 = fmaxf(gg.y * ((v.y - muf) * inv) + bb.y, 0.0f);
    float r2 = fmaxf(gg.z * ((v.z - muf) * inv) + bb.z, 0.0f);
    float r3 = fmaxf(gg.w * ((v.w - muf) * inv) + bb.w, 0.0f);
    size_t row = (i * 4) >> 8;
    size_t base = row * 512 + c;
    __nv_bfloat16 h4[4], l4[4];
    split2(r0, h4[0], l4[0]); split2(r1, h4[1], l4[1]);
    split2(r2, h4[2], l4[2]); split2(r3, h4[3], l4[3]);
    *(__nv_bfloat162*)(g_A_hi + base)     = __nv_bfloat162(h4[0], h4[1]);
    *(__nv_bfloat162*)(g_A_hi + base + 2) = __nv_bfloat162(h4[2], h4[3]);
    *(__nv_bfloat162*)(g_A_lo + base)     = __nv_bfloat162(l4[0], l4[1]);
    *(__nv_bfloat162*)(g_A_lo + base + 2) = __nv_bfloat162(l4[2], l4[3]);
}

// ------------------------- launch -------------------------
extern "C" void kernel_launch(void* const* d_in, const int* in_sizes, int n_in,
                              void* d_out, int out_size) {
    const float* x       = (const float*)d_in[0];
    const int*   ei      = (const int*)  d_in[1];
    const float* lin1_w  = (const float*)d_in[2];
    const float* lin1_b  = (const float*)d_in[3];
    const float* conv_w1 = (const float*)d_in[4];
    const float* conv_w2 = (const float*)d_in[5];
    const float* gamma   = (const float*)d_in[6];
    const float* betaa   = (const float*)d_in[7];
    const float* lin2_w  = (const float*)d_in[8];
    const float* lin2_b  = (const float*)d_in[9];
    float* out = (float*)d_out;

    static int inited = 0;
    static cudaStream_t s2;
    static cudaEvent_t evFork, evR[NL];
    if (!inited) {
        cudaFuncSetAttribute(k_mma, cudaFuncAttributeMaxDynamicSharedMemorySize, SM_TOTAL);
        cudaStreamCreateWithFlags(&s2, cudaStreamNonBlocking);
        cudaEventCreateWithFlags(&evFork, cudaEventDisableTiming);
        for (int l = 0; l < NL; l++)
            cudaEventCreateWithFlags(&evR[l], cudaEventDisableTiming);
        inited = 1;
    }

    // graph normalization + CSR build
    k_init<<<(NN + 255) / 256, 256>>>();
    k_edge_count<<<(NE + 255) / 256, 256>>>(ei);
    k_rsqrt<<<(NN + 255) / 256, 256>>>();
    k_scan_part<<<49, 1024>>>();
    k_scan_top<<<1, 32>>>();
    k_scan_out<<<49, 1024>>>();
    k_cursor<<<(NN + 255) / 256, 256>>>();
    k_scatter<<<(NE + 255) / 256, 256>>>(ei);

    // bf16 operand prep
    k_prep_w<<<(WB_TOT + 255) / 256, 256>>>(lin1_w, conv_w1, conv_w2, lin2_w);
    k_prep_x<<<(NN * D_IN + 255) / 256, 256>>>(x);

    const int MT = (NN + 127) / 128;  // 391

    // lin1 + relu -> g_x0 (+ 0.5*x0 splits)
    k_mma<<<dim3(2, MT), 256, SM_TOTAL>>>(1, WB_L1, 128, 128, 256, lin1_b, nullptr, 0);

    // fork: all 8 GEMM_r on s2 (depend only on x0 splits)
    cudaEventRecord(evFork, 0);
    cudaStreamWaitEvent(s2, evFork, 0);
    for (int l = 0; l < NL; l++) {
        k_mma<<<dim3(2, MT), 256, SM_TOTAL, s2>>>(0, WB_LYR + l * 131072 + 256, 256, 512, 256,
                                                  nullptr, nullptr, l);
        cudaEventRecord(evR[l], s2);
    }

    // main chain: SpMM_l -> (join GEMM_r_l) -> GEMM_t_l
    for (int l = 0; l < NL; l++) {
        k_spmm<<<(NN + 7) / 8, 256>>>(l, gamma + (size_t)(l > 0 ? l - 1 : 0) * D_HID,
                                      betaa + (size_t)(l > 0 ? l - 1 : 0) * D_HID);
        cudaStreamWaitEvent(0, evR[l], 0);
        k_mma<<<dim3(2, MT), 256, SM_TOTAL>>>(2, WB_LYR + l * 131072, 256, 512, 256,
                                              nullptr, nullptr, l);
    }

    // final norm (layer 7 params) -> lin2 input splits
    k_norm_final<<<(NN * D_HID / 4 + 255) / 256, 256>>>(gamma + 7 * (size_t)D_HID,
                                                        betaa + 7 * (size_t)D_HID);

    // lin2 + relu -> out
    k_mma<<<dim3(1, MT), 256, SM_TOTAL>>>(3, WB_L2, 256, 256, 128, lin2_b, out, 0);

    (void)in_sizes; (void)n_in; (void)out_size;
}

// round 7
// speedup vs baseline: 1.6161x; 1.1867x over previous
#include <cuda_runtime.h>
#include <cuda_bf16.h>
#include <math.h>
#include <stdint.h>

#define NN   50000
#define NE   800000
#define D_IN 128
#define D_HID 256
#define D_OUT 128
#define NL   8

// ---------------- weight buffer layout (transposed, K-major [N][K]) ------
#define WB_L1   0                         // lin1: [256][128]
#define WB_LYR  32768                     // layers: 8 x [256][512]  (W' = beta*W + omb*I)
#define WB_L2   (32768 + 8 * 131072)      // lin2: [128][256]
#define WB_TOT  (WB_L2 + 32768)

// ------------------------- static device scratch -------------------------
__device__ float  g_dis[NN];
__device__ int    g_rowptr[NN + 1];
__device__ int    g_cnt[NN];
__device__ int    g_bsum[64];
__device__ int    g_boff[64];
__device__ int    g_src[NE];
__device__ float  g_w[NE];
__device__ float  g_x0[(size_t)NN * D_HID];
__device__ float  g_h [(size_t)NN * D_HID];
__device__ double g_accA[2][2];           // [parity][sum, sumsq]
// bf16 split operands
__device__ __nv_bfloat16 g_A_hi[(size_t)NN * 512];   // cols 0..255: t (or h_norm) ; 256..511: 0.5*x0
__device__ __nv_bfloat16 g_A_lo[(size_t)NN * 512];
__device__ __nv_bfloat16 g_xin_hi[(size_t)NN * D_IN];
__device__ __nv_bfloat16 g_xin_lo[(size_t)NN * D_IN];
__device__ __nv_bfloat16 g_Bw_hi[WB_TOT];
__device__ __nv_bfloat16 g_Bw_lo[WB_TOT];

// ------------------------- helpers -------------------------
__device__ __forceinline__ uint32_t smem_u32(const void* p) {
    uint32_t a;
    asm("{ .reg .u64 t; cvta.to.shared.u64 t, %1; cvt.u32.u64 %0, t; }" : "=r"(a) : "l"(p));
    return a;
}
__device__ __forceinline__ void cp16(uint32_t dst, const void* src) {
    asm volatile("cp.async.cg.shared.global [%0], [%1], 16;" :: "r"(dst), "l"(src));
}
#define CP_COMMIT() asm volatile("cp.async.commit_group;" ::: "memory")
#define CP_WAIT1()  asm volatile("cp.async.wait_group 1;" ::: "memory")

__device__ __forceinline__ void ldm_x4(uint32_t* r, uint32_t addr) {
    asm volatile("ldmatrix.sync.aligned.m8n8.x4.shared.b16 {%0,%1,%2,%3}, [%4];"
                 : "=r"(r[0]), "=r"(r[1]), "=r"(r[2]), "=r"(r[3]) : "r"(addr));
}
__device__ __forceinline__ void mma16816(float* c, const uint32_t* a, const uint32_t* b) {
    asm volatile("mma.sync.aligned.m16n8k16.row.col.f32.bf16.bf16.f32 "
                 "{%0,%1,%2,%3}, {%4,%5,%6,%7}, {%8,%9}, {%0,%1,%2,%3};"
                 : "+f"(c[0]), "+f"(c[1]), "+f"(c[2]), "+f"(c[3])
                 : "r"(a[0]), "r"(a[1]), "r"(a[2]), "r"(a[3]), "r"(b[0]), "r"(b[1]));
}
__device__ __forceinline__ void split2(float v, __nv_bfloat16& h, __nv_bfloat16& l) {
    h = __float2bfloat16(v);
    l = __float2bfloat16(v - __bfloat162float(h));
}

// ------------------------- setup kernels -------------------------
__global__ void k_zero() {
    int i = blockIdx.x * blockDim.x + threadIdx.x;
    if (i < NN) g_cnt[i] = 0;
}
__global__ void k_count(const int* __restrict__ ei) {
    int e = blockIdx.x * blockDim.x + threadIdx.x;
    if (e < NE) atomicAdd(&g_cnt[ei[NE + e]], 1);
}
__device__ __forceinline__ int block_scan_inc(int v, int* wsum) {
    int lane = threadIdx.x & 31, wid = threadIdx.x >> 5;
#pragma unroll
    for (int o = 1; o < 32; o <<= 1) { int t = __shfl_up_sync(~0u, v, o); if (lane >= o) v += t; }
    if (lane == 31) wsum[wid] = v;
    __syncthreads();
    if (wid == 0) {
        int w = wsum[lane];
#pragma unroll
        for (int o = 1; o < 32; o <<= 1) { int t = __shfl_up_sync(~0u, w, o); if (lane >= o) w += t; }
        wsum[lane] = w;
    }
    __syncthreads();
    return v + (wid > 0 ? wsum[wid - 1] : 0);
}
__global__ void k_scan_part() {
    __shared__ int wsum[32];
    int i = blockIdx.x * 1024 + threadIdx.x;
    int v = (i < NN) ? g_cnt[i] : 0;
    int inc = block_scan_inc(v, wsum);
    if (threadIdx.x == 1023) g_bsum[blockIdx.x] = inc;
}
__global__ void k_scan_top() {
    if (threadIdx.x == 0) {
        int run = 0;
        for (int b = 0; b < 49; b++) { g_boff[b] = run; run += g_bsum[b]; }
        g_rowptr[NN] = run;
    }
}
// exclusive rowptr + deg^{-1/2} + cursor copy (g_cnt <- rowptr), one pass
__global__ void k_scan_out() {
    __shared__ int wsum[32];
    int i = blockIdx.x * 1024 + threadIdx.x;
    int v = (i < NN) ? g_cnt[i] : 0;
    int inc = block_scan_inc(v, wsum);
    if (i < NN) {
        int rp = g_boff[blockIdx.x] + inc - v;
        g_rowptr[i] = rp;
        g_cnt[i] = rp;                       // scatter cursor
        g_dis[i] = rsqrtf((float)(v + 1));   // self loop adds 1
    }
}
__global__ void k_scatter(const int* __restrict__ ei) {
    int e = blockIdx.x * blockDim.x + threadIdx.x;
    if (e < NE) {
        int r = ei[e];
        int c = ei[NE + e];
        int s = atomicAdd(&g_cnt[c], 1);
        g_src[s] = r;
        g_w[s]   = g_dis[r] * g_dis[c];
    }
}

// ------------------------- weight / input prep (bf16 splits) -------------
__global__ void k_prep_w(const float* __restrict__ lin1_w, const float* __restrict__ w1,
                         const float* __restrict__ w2, const float* __restrict__ lin2_w) {
    int idx = blockIdx.x * blockDim.x + threadIdx.x;
    if (idx >= WB_TOT) return;
    float v;
    if (idx < WB_LYR) {                       // lin1: [n=256][k=128]
        int n = idx >> 7, k = idx & 127;
        v = lin1_w[k * 256 + n];
    } else if (idx < WB_L2) {                 // layer l: [n=256][k=512]
        int r = idx - WB_LYR;
        int l = r >> 17;
        int q = r & 131071;
        int n = q >> 9, k = q & 511;
        float beta = logf((float)(l + 2) / (float)(l + 1));
        float omb = 1.0f - beta;
        if (k < 256) v = beta * w1[l * 65536 + k * 256 + n] + ((k == n) ? omb : 0.0f);
        else {
            int k2 = k - 256;
            v = beta * w2[l * 65536 + k2 * 256 + n] + ((k2 == n) ? omb : 0.0f);
        }
    } else {                                  // lin2: [n=128][k=256]
        int r = idx - WB_L2;
        int n = r >> 8, k = r & 255;
        v = lin2_w[k * 128 + n];
    }
    __nv_bfloat16 h, l;
    split2(v, h, l);
    g_Bw_hi[idx] = h;
    g_Bw_lo[idx] = l;
}
__global__ void k_prep_x(const float* __restrict__ x) {
    size_t idx = (size_t)blockIdx.x * blockDim.x + threadIdx.x;
    if (idx >= (size_t)NN * D_IN) return;
    __nv_bfloat16 h, l;
    split2(x[idx], h, l);
    g_xin_hi[idx] = h;
    g_xin_lo[idx] = l;
}

// ------------------------- SpMM with fused norm+relu on gather -----------
__global__ void __launch_bounds__(256) k_spmm(int l, const float* __restrict__ gam,
                                              const float* __restrict__ bet) {
    int par = l & 1;
    if (blockIdx.x == 0 && threadIdx.x == 0) { g_accA[par][0] = 0.0; g_accA[par][1] = 0.0; }
    int warp = (blockIdx.x * blockDim.x + threadIdx.x) >> 5;
    int lane = threadIdx.x & 31;
    if (warp >= NN) return;
    const float* __restrict__ h = (l == 0) ? g_x0 : g_h;

    float4 ca0, cb0, ca1, cb1;
    if (l == 0) {
        ca0 = ca1 = make_float4(1.f, 1.f, 1.f, 1.f);
        cb0 = cb1 = make_float4(0.f, 0.f, 0.f, 0.f);
    } else {
        int pp = (l - 1) & 1;
        double cnt = (double)NN * (double)D_HID;
        double mu = g_accA[pp][0] / cnt;
        double var = g_accA[pp][1] / cnt - mu * mu;
        if (var < 0.0) var = 0.0;
        float inv = (float)(1.0 / (sqrt(var) + 1e-5));
        float muf = (float)mu;
        int c0 = lane * 4, c1 = 128 + lane * 4;
        float4 g0 = *(const float4*)(gam + c0), g1 = *(const float4*)(gam + c1);
        float4 b0 = *(const float4*)(bet + c0), b1 = *(const float4*)(bet + c1);
        ca0 = make_float4(g0.x * inv, g0.y * inv, g0.z * inv, g0.w * inv);
        ca1 = make_float4(g1.x * inv, g1.y * inv, g1.z * inv, g1.w * inv);
        cb0 = make_float4(b0.x - muf * ca0.x, b0.y - muf * ca0.y, b0.z - muf * ca0.z, b0.w - muf * ca0.w);
        cb1 = make_float4(b1.x - muf * ca1.x, b1.y - muf * ca1.y, b1.z - muf * ca1.z, b1.w - muf * ca1.w);
    }

    int c = warp;
    float dc = g_dis[c];
    float wself = dc * dc;
    const float4* hr = (const float4*)(h + (size_t)c * D_HID);
    float4 v0 = hr[lane], v1 = hr[lane + 32];
    float4 a0, a1;
    a0.x = wself * fmaxf(ca0.x * v0.x + cb0.x, 0.f);
    a0.y = wself * fmaxf(ca0.y * v0.y + cb0.y, 0.f);
    a0.z = wself * fmaxf(ca0.z * v0.z + cb0.z, 0.f);
    a0.w = wself * fmaxf(ca0.w * v0.w + cb0.w, 0.f);
    a1.x = wself * fmaxf(ca1.x * v1.x + cb1.x, 0.f);
    a1.y = wself * fmaxf(ca1.y * v1.y + cb1.y, 0.f);
    a1.z = wself * fmaxf(ca1.z * v1.z + cb1.z, 0.f);
    a1.w = wself * fmaxf(ca1.w * v1.w + cb1.w, 0.f);

    int beg = g_rowptr[c], end = g_rowptr[c + 1];
#pragma unroll 4
    for (int e = beg; e < end; e++) {
        int   s = __ldg(&g_src[e]);
        float w = __ldg(&g_w[e]);
        const float4* hs = (const float4*)(h + (size_t)s * D_HID);
        float4 b0 = __ldg(&hs[lane]);
        float4 b1 = __ldg(&hs[lane + 32]);
        a0.x += w * fmaxf(ca0.x * b0.x + cb0.x, 0.f);
        a0.y += w * fmaxf(ca0.y * b0.y + cb0.y, 0.f);
        a0.z += w * fmaxf(ca0.z * b0.z + cb0.z, 0.f);
        a0.w += w * fmaxf(ca0.w * b0.w + cb0.w, 0.f);
        a1.x += w * fmaxf(ca1.x * b1.x + cb1.x, 0.f);
        a1.y += w * fmaxf(ca1.y * b1.y + cb1.y, 0.f);
        a1.z += w * fmaxf(ca1.z * b1.z + cb1.z, 0.f);
        a1.w += w * fmaxf(ca1.w * b1.w + cb1.w, 0.f);
    }
    __nv_bfloat16* Ah = g_A_hi + (size_t)c * 512;
    __nv_bfloat16* Al = g_A_lo + (size_t)c * 512;
    float vv[8] = {0.5f * a0.x, 0.5f * a0.y, 0.5f * a0.z, 0.5f * a0.w,
                   0.5f * a1.x, 0.5f * a1.y, 0.5f * a1.z, 0.5f * a1.w};
    int cols[2] = {lane * 4, 128 + lane * 4};
#pragma unroll
    for (int g = 0; g < 2; g++) {
        __nv_bfloat16 h4[4], l4[4];
#pragma unroll
        for (int j = 0; j < 4; j++) split2(vv[g * 4 + j], h4[j], l4[j]);
        *(__nv_bfloat162*)(Ah + cols[g])     = __nv_bfloat162(h4[0], h4[1]);
        *(__nv_bfloat162*)(Ah + cols[g] + 2) = __nv_bfloat162(h4[2], h4[3]);
        *(__nv_bfloat162*)(Al + cols[g])     = __nv_bfloat162(l4[0], l4[1]);
        *(__nv_bfloat162*)(Al + cols[g] + 2) = __nv_bfloat162(l4[2], l4[3]);
    }
}

// ------------------------- mma.sync GEMM (8 warps, 3-stage) --------------
// mode 1: lin1   A=xin (lda=128), K=128    : relu(acc+bias)->g_x0 + 0.5x0 splits
// mode 2: layer  A=g_A (lda=512), K=512    : acc -> g_h + sums (W' pre-fused)
// mode 3: lin2   A=g_A (lda=512), K=256    : relu(acc+bias)->Cout
#define STG_SZ 40960
#define NSTG 3
#define SM_TOTAL (NSTG * STG_SZ)

__global__ void __launch_bounds__(256) k_mma(int mode, int bOff, int K, int ldb, int N,
                                             const float* __restrict__ bias,
                                             float* __restrict__ Cout, int parity) {
    extern __shared__ char smem[];
    uint32_t sb = smem_u32(smem);
    int tid = threadIdx.x;
    int lane = tid & 31, wrp = tid >> 5;
    int wm = wrp & 1, wn = wrp >> 1;
    int m0 = blockIdx.y * 128, n0 = blockIdx.x * 128;

    const __nv_bfloat16* Ahi = (mode == 1) ? g_xin_hi : g_A_hi;
    const __nv_bfloat16* Alo = (mode == 1) ? g_xin_lo : g_A_lo;
    const int lda = (mode == 1) ? 128 : 512;
    const __nv_bfloat16* Bhi = g_Bw_hi + bOff;
    const __nv_bfloat16* Blo = g_Bw_lo + bOff;

    const int nch = K / 32;

    int r0i = tid >> 2, seg0 = (tid & 3);
    int r1i = (tid + 256) >> 2;

    auto load_stage = [&](int s, int ch) {
        int kb = ch * 32;
        uint32_t base = sb + s * STG_SZ;
        int gr0 = m0 + r0i; if (gr0 >= NN) gr0 = 0;
        int gr1 = m0 + r1i; if (gr1 >= NN) gr1 = 0;
        const __nv_bfloat16* a0h = Ahi + (size_t)gr0 * lda + kb + seg0 * 8;
        const __nv_bfloat16* a1h = Ahi + (size_t)gr1 * lda + kb + seg0 * 8;
        const __nv_bfloat16* a0l = Alo + (size_t)gr0 * lda + kb + seg0 * 8;
        const __nv_bfloat16* a1l = Alo + (size_t)gr1 * lda + kb + seg0 * 8;
        uint32_t d0 = base + r0i * 80 + seg0 * 16;
        uint32_t d1 = base + r1i * 80 + seg0 * 16;
        cp16(d0, a0h);          cp16(d1, a1h);
        cp16(d0 + 10240, a0l);  cp16(d1 + 10240, a1l);
        const __nv_bfloat16* b0h = Bhi + (size_t)(n0 + r0i) * ldb + kb + seg0 * 8;
        const __nv_bfloat16* b1h = Bhi + (size_t)(n0 + r1i) * ldb + kb + seg0 * 8;
        const __nv_bfloat16* b0l = Blo + (size_t)(n0 + r0i) * ldb + kb + seg0 * 8;
        const __nv_bfloat16* b1l = Blo + (size_t)(n0 + r1i) * ldb + kb + seg0 * 8;
        cp16(d0 + 20480, b0h);  cp16(d1 + 20480, b1h);
        cp16(d0 + 30720, b0l);  cp16(d1 + 30720, b1l);
    };

    float acc[4][4][4];
#pragma unroll
    for (int i = 0; i < 4; i++)
#pragma unroll
        for (int j = 0; j < 4; j++)
#pragma unroll
            for (int p = 0; p < 4; p++) acc[i][j][p] = 0.0f;

    load_stage(0, 0); CP_COMMIT();
    load_stage(1, 1); CP_COMMIT();

    int a_row = wm * 64 + (lane & 7) + ((lane >> 3) & 1) * 8;
    int a_colh = (lane >> 4) * 8;
    // B x4 addressing: lanes 0-7 matrix0 (n0..7,k0..7), 8-15 (n0..7,k8..15),
    // 16-23 (n8..15,k0..7), 24-31 (n8..15,k8..15)
    int b_row2 = wn * 32 + ((lane >> 4) & 1) * 8 + (lane & 7);
    int b_colh = ((lane >> 3) & 1) * 8;

    for (int ch = 0; ch < nch; ch++) {
        int st = ch % NSTG;
        CP_WAIT1();
        __syncthreads();
        if (ch + 2 < nch) load_stage((ch + 2) % NSTG, ch + 2);
        CP_COMMIT();
        uint32_t base = sb + st * STG_SZ;
#pragma unroll
        for (int k16 = 0; k16 < 2; k16++) {
            uint32_t ah[4][4], al[4][4], bh[4][2], bl[4][2];
#pragma unroll
            for (int mt = 0; mt < 4; mt++) {
                uint32_t ad = base + (a_row + mt * 16) * 80 + (k16 * 16 + a_colh) * 2;
                ldm_x4(ah[mt], ad);
                ldm_x4(al[mt], ad + 10240);
            }
#pragma unroll
            for (int np = 0; np < 2; np++) {
                uint32_t bd = base + 20480 + (b_row2 + np * 16) * 80 + (k16 * 16 + b_colh) * 2;
                uint32_t r4[4];
                ldm_x4(r4, bd);
                bh[np * 2][0] = r4[0]; bh[np * 2][1] = r4[1];
                bh[np * 2 + 1][0] = r4[2]; bh[np * 2 + 1][1] = r4[3];
                ldm_x4(r4, bd + 10240);
                bl[np * 2][0] = r4[0]; bl[np * 2][1] = r4[1];
                bl[np * 2 + 1][0] = r4[2]; bl[np * 2 + 1][1] = r4[3];
            }
#pragma unroll
            for (int mt = 0; mt < 4; mt++)
#pragma unroll
                for (int nt = 0; nt < 4; nt++) {
                    mma16816(acc[mt][nt], ah[mt], bh[nt]);
                    mma16816(acc[mt][nt], al[mt], bh[nt]);
                    mma16816(acc[mt][nt], ah[mt], bl[nt]);
                }
        }
    }

    // ------------- epilogue -------------
    float sum = 0.0f, ssum = 0.0f;
    int rbase = m0 + wm * 64 + (lane >> 2);
    int cbase = n0 + wn * 32 + (lane & 3) * 2;
#pragma unroll
    for (int mt = 0; mt < 4; mt++) {
#pragma unroll
        for (int half = 0; half < 2; half++) {
            int row = rbase + mt * 16 + half * 8;
            if (row >= NN) continue;
#pragma unroll
            for (int nt = 0; nt < 4; nt++) {
                int c = cbase + nt * 8;
                float v0 = acc[mt][nt][half * 2 + 0];
                float v1 = acc[mt][nt][half * 2 + 1];
                if (mode == 2) {
                    size_t idx = (size_t)row * 256 + c;
                    *(float2*)(g_h + idx) = make_float2(v0, v1);
                    sum += v0 + v1;
                    ssum += v0 * v0 + v1 * v1;
                } else if (mode == 1) {
                    float r0 = fmaxf(v0 + __ldg(&bias[c]), 0.0f);
                    float r1 = fmaxf(v1 + __ldg(&bias[c + 1]), 0.0f);
                    *(float2*)(g_x0 + (size_t)row * 256 + c) = make_float2(r0, r1);
                    __nv_bfloat16 h0, l0, h1, l1;
                    split2(0.5f * r0, h0, l0);
                    split2(0.5f * r1, h1, l1);
                    size_t sidx = (size_t)row * 512 + 256 + c;
                    *(__nv_bfloat162*)(g_A_hi + sidx) = __nv_bfloat162(h0, h1);
                    *(__nv_bfloat162*)(g_A_lo + sidx) = __nv_bfloat162(l0, l1);
                } else {
                    float r0 = fmaxf(v0 + __ldg(&bias[c]), 0.0f);
                    float r1 = fmaxf(v1 + __ldg(&bias[c + 1]), 0.0f);
                    *(float2*)(Cout + (size_t)row * N + c) = make_float2(r0, r1);
                }
            }
        }
    }
    if (mode == 2) {
#pragma unroll
        for (int off = 16; off > 0; off >>= 1) {
            sum  += __shfl_down_sync(0xffffffffu, sum, off);
            ssum += __shfl_down_sync(0xffffffffu, ssum, off);
        }
        __syncthreads();
        float* rs  = (float*)smem;
        float* rss = (float*)smem + 32;
        if (lane == 0) { rs[wrp] = sum; rss[wrp] = ssum; }
        __syncthreads();
        if (tid == 0) {
            float S = 0.f, SS = 0.f;
            for (int w = 0; w < 8; w++) { S += rs[w]; SS += rss[w]; }
            atomicAdd(&g_accA[parity][0], (double)S);
            atomicAdd(&g_accA[parity][1], (double)SS);
        }
    }
}

// ------------------------- final norm -> lin2 input splits ---------------
__global__ void k_norm_final(const float* __restrict__ gam, const float* __restrict__ bet) {
    double cnt = (double)NN * (double)D_HID;
    double mu = g_accA[1][0] / cnt;
    double var = g_accA[1][1] / cnt - mu * mu;
    if (var < 0.0) var = 0.0;
    float inv = (float)(1.0 / (sqrt(var) + 1e-5));
    float muf = (float)mu;
    size_t total = (size_t)NN * D_HID / 4;
    size_t i = (size_t)blockIdx.x * blockDim.x + threadIdx.x;
    if (i >= total) return;
    float4 v = ((const float4*)g_h)[i];
    int c = (int)((i * 4) & (D_HID - 1));
    float4 gg = *(const float4*)(gam + c);
    float4 bb = *(const float4*)(bet + c);
    float r0 = fmaxf(gg.x * ((v.x - muf) * inv) + bb.x, 0.0f);
    float r1 = fmaxf(gg.y * ((v.y - muf) * inv) + bb.y, 0.0f);
    float r2 = fmaxf(gg.z * ((v.z - muf) * inv) + bb.z, 0.0f);
    float r3 = fmaxf(gg.w * ((v.w - muf) * inv) + bb.w, 0.0f);
    size_t row = (i * 4) >> 8;
    size_t base = row * 512 + c;
    __nv_bfloat16 h4[4], l4[4];
    split2(r0, h4[0], l4[0]); split2(r1, h4[1], l4[1]);
    split2(r2, h4[2], l4[2]); split2(r3, h4[3], l4[3]);
    *(__nv_bfloat162*)(g_A_hi + base)     = __nv_bfloat162(h4[0], h4[1]);
    *(__nv_bfloat162*)(g_A_hi + base + 2) = __nv_bfloat162(h4[2], h4[3]);
    *(__nv_bfloat162*)(g_A_lo + base)     = __nv_bfloat162(l4[0], l4[1]);
    *(__nv_bfloat162*)(g_A_lo + base + 2) = __nv_bfloat162(l4[2], l4[3]);
}

// ------------------------- launch -------------------------
extern "C" void kernel_launch(void* const* d_in, const int* in_sizes, int n_in,
                              void* d_out, int out_size) {
    const float* x       = (const float*)d_in[0];
    const int*   ei      = (const int*)  d_in[1];
    const float* lin1_w  = (const float*)d_in[2];
    const float* lin1_b  = (const float*)d_in[3];
    const float* conv_w1 = (const float*)d_in[4];
    const float* conv_w2 = (const float*)d_in[5];
    const float* gamma   = (const float*)d_in[6];
    const float* betaa   = (const float*)d_in[7];
    const float* lin2_w  = (const float*)d_in[8];
    const float* lin2_b  = (const float*)d_in[9];
    float* out = (float*)d_out;

    static int smem_set = 0;
    if (!smem_set) {
        cudaFuncSetAttribute(k_mma, cudaFuncAttributeMaxDynamicSharedMemorySize, SM_TOTAL);
        smem_set = 1;
    }

    // CSR build (by destination) + deg^{-1/2}
    k_zero<<<(NN + 255) / 256, 256>>>();
    k_count<<<(NE + 255) / 256, 256>>>(ei);
    k_scan_part<<<49, 1024>>>();
    k_scan_top<<<1, 32>>>();
    k_scan_out<<<49, 1024>>>();
    k_scatter<<<(NE + 255) / 256, 256>>>(ei);

    // bf16 operand prep
    k_prep_w<<<(WB_TOT + 255) / 256, 256>>>(lin1_w, conv_w1, conv_w2, lin2_w);
    k_prep_x<<<(NN * D_IN + 255) / 256, 256>>>(x);

    const int MT = (NN + 127) / 128;  // 391

    // lin1 + relu -> g_x0 (+ 0.5*x0 splits)
    k_mma<<<dim3(2, MT), 256, SM_TOTAL>>>(1, WB_L1, 128, 128, 256, lin1_b, nullptr, 0);

    // 8 GCNII layers: SpMM(fused prev-norm) -> GEMM K=512 (W' pre-fused)
    for (int l = 0; l < NL; l++) {
        k_spmm<<<(NN + 7) / 8, 256>>>(l, gamma + (size_t)(l > 0 ? l - 1 : 0) * D_HID,
                                      betaa + (size_t)(l > 0 ? l - 1 : 0) * D_HID);
        k_mma<<<dim3(2, MT), 256, SM_TOTAL>>>(2, WB_LYR + l * 131072, 512, 512, 256,
                                              nullptr, nullptr, l & 1);
    }

    // final norm (layer 7 params) -> lin2 input splits
    k_norm_final<<<(NN * D_HID / 4 + 255) / 256, 256>>>(gamma + 7 * (size_t)D_HID,
                                                        betaa + 7 * (size_t)D_HID);

    // lin2 + relu -> out
    k_mma<<<dim3(1, MT), 256, SM_TOTAL>>>(3, WB_L2, 256, 256, 128, lin2_b, out, 0);

    (void)in_sizes; (void)n_in; (void)out_size;
}

// round 9
// speedup vs baseline: 1.7475x; 1.0813x over previous
#include <cuda_runtime.h>
#include <cuda_bf16.h>
#include <math.h>
#include <stdint.h>

#define NN   50000
#define NE   800000
#define D_IN 128
#define D_HID 256
#define D_OUT 128
#define NL   8

// ---------------- weight buffer layout (transposed, K-major [N][K]) ------
#define WB_L1   0                         // lin1: [256][128]
#define WB_LYR  32768                     // layers: 8 x [256][512]  (W' = beta*W + omb*I)
#define WB_L2   (32768 + 8 * 131072)      // lin2: [128][256]
#define WB_TOT  (WB_L2 + 32768)

// ------------------------- static device scratch -------------------------
__device__ float  g_dis[NN];
__device__ int    g_rowptr[NN + 1];
__device__ int    g_cnt[NN];
__device__ int    g_bsum[64];
__device__ int    g_boff[64];
__device__ int    g_src[NE];
__device__ float  g_w[NE];
__device__ float  g_x0[(size_t)NN * D_HID];
__device__ float  g_h [(size_t)NN * D_HID];
__device__ double g_accA[2][2];           // [parity][sum, sumsq]
// bf16 split operands
__device__ __nv_bfloat16 g_A_hi[(size_t)NN * 512];   // cols 0..255: t (or h_norm) ; 256..511: 0.5*x0
__device__ __nv_bfloat16 g_A_lo[(size_t)NN * 512];
__device__ __nv_bfloat16 g_xin_hi[(size_t)NN * D_IN];
__device__ __nv_bfloat16 g_xin_lo[(size_t)NN * D_IN];
__device__ __nv_bfloat16 g_Bw_hi[WB_TOT];
__device__ __nv_bfloat16 g_Bw_lo[WB_TOT];

// ------------------------- helpers -------------------------
__device__ __forceinline__ uint32_t smem_u32(const void* p) {
    uint32_t a;
    asm("{ .reg .u64 t; cvta.to.shared.u64 t, %1; cvt.u32.u64 %0, t; }" : "=r"(a) : "l"(p));
    return a;
}
__device__ __forceinline__ void cp16(uint32_t dst, const void* src) {
    asm volatile("cp.async.cg.shared.global [%0], [%1], 16;" :: "r"(dst), "l"(src));
}
#define CP_COMMIT() asm volatile("cp.async.commit_group;" ::: "memory")
#define CP_WAIT1()  asm volatile("cp.async.wait_group 1;" ::: "memory")

__device__ __forceinline__ void ldm_x4(uint32_t* r, uint32_t addr) {
    asm volatile("ldmatrix.sync.aligned.m8n8.x4.shared.b16 {%0,%1,%2,%3}, [%4];"
                 : "=r"(r[0]), "=r"(r[1]), "=r"(r[2]), "=r"(r[3]) : "r"(addr));
}
__device__ __forceinline__ void mma16816(float* c, const uint32_t* a, const uint32_t* b) {
    asm volatile("mma.sync.aligned.m16n8k16.row.col.f32.bf16.bf16.f32 "
                 "{%0,%1,%2,%3}, {%4,%5,%6,%7}, {%8,%9}, {%0,%1,%2,%3};"
                 : "+f"(c[0]), "+f"(c[1]), "+f"(c[2]), "+f"(c[3])
                 : "r"(a[0]), "r"(a[1]), "r"(a[2]), "r"(a[3]), "r"(b[0]), "r"(b[1]));
}
__device__ __forceinline__ void split2(float v, __nv_bfloat16& h, __nv_bfloat16& l) {
    h = __float2bfloat16(v);
    l = __float2bfloat16(v - __bfloat162float(h));
}

// ------------------------- setup kernels -------------------------
__global__ void k_zero() {
    int i = blockIdx.x * blockDim.x + threadIdx.x;
    if (i < NN) g_cnt[i] = 0;
}
__global__ void k_count(const int* __restrict__ ei) {
    int e = blockIdx.x * blockDim.x + threadIdx.x;
    if (e < NE) atomicAdd(&g_cnt[ei[NE + e]], 1);
}
__device__ __forceinline__ int block_scan_inc(int v, int* wsum) {
    int lane = threadIdx.x & 31, wid = threadIdx.x >> 5;
#pragma unroll
    for (int o = 1; o < 32; o <<= 1) { int t = __shfl_up_sync(~0u, v, o); if (lane >= o) v += t; }
    if (lane == 31) wsum[wid] = v;
    __syncthreads();
    if (wid == 0) {
        int w = wsum[lane];
#pragma unroll
        for (int o = 1; o < 32; o <<= 1) { int t = __shfl_up_sync(~0u, w, o); if (lane >= o) w += t; }
        wsum[lane] = w;
    }
    __syncthreads();
    return v + (wid > 0 ? wsum[wid - 1] : 0);
}
__global__ void k_scan_part() {
    __shared__ int wsum[32];
    int i = blockIdx.x * 1024 + threadIdx.x;
    int v = (i < NN) ? g_cnt[i] : 0;
    int inc = block_scan_inc(v, wsum);
    if (threadIdx.x == 1023) g_bsum[blockIdx.x] = inc;
}
// one warp: parallel scan of 49 block sums (2 rounds of 32)
__global__ void k_scan_top() {
    int lane = threadIdx.x;
    int v0 = (lane < 49) ? g_bsum[lane] : 0;
    int v1 = (lane + 32 < 49) ? g_bsum[lane + 32] : 0;
    int s0 = v0;
#pragma unroll
    for (int o = 1; o < 32; o <<= 1) { int t = __shfl_up_sync(~0u, s0, o); if (lane >= o) s0 += t; }
    int tot0 = __shfl_sync(~0u, s0, 31);
    int s1 = v1;
#pragma unroll
    for (int o = 1; o < 32; o <<= 1) { int t = __shfl_up_sync(~0u, s1, o); if (lane >= o) s1 += t; }
    int tot1 = __shfl_sync(~0u, s1, 31);       // converged: all lanes participate
    g_boff[lane] = s0 - v0;                     // lanes 0..31
    if (lane + 32 < 49) g_boff[lane + 32] = tot0 + s1 - v1;
    if (lane == 0) g_rowptr[NN] = tot0 + tot1;
}
// exclusive rowptr + deg^{-1/2} + cursor copy (g_cnt <- rowptr), one pass
__global__ void k_scan_out() {
    __shared__ int wsum[32];
    int i = blockIdx.x * 1024 + threadIdx.x;
    int v = (i < NN) ? g_cnt[i] : 0;
    int inc = block_scan_inc(v, wsum);
    if (i < NN) {
        int rp = g_boff[blockIdx.x] + inc - v;
        g_rowptr[i] = rp;
        g_cnt[i] = rp;                       // scatter cursor
        g_dis[i] = rsqrtf((float)(v + 1));   // self loop adds 1
    }
}
__global__ void k_scatter(const int* __restrict__ ei) {
    int e = blockIdx.x * blockDim.x + threadIdx.x;
    if (e < NE) {
        int r = ei[e];
        int c = ei[NE + e];
        int s = atomicAdd(&g_cnt[c], 1);
        g_src[s] = r;
        g_w[s]   = g_dis[r] * g_dis[c];
    }
}

// ------------------------- weight / input prep (bf16 splits) -------------
__global__ void k_prep_w(const float* __restrict__ lin1_w, const float* __restrict__ w1,
                         const float* __restrict__ w2, const float* __restrict__ lin2_w) {
    int idx = blockIdx.x * blockDim.x + threadIdx.x;
    if (idx >= WB_TOT) return;
    float v;
    if (idx < WB_LYR) {                       // lin1: [n=256][k=128]
        int n = idx >> 7, k = idx & 127;
        v = lin1_w[k * 256 + n];
    } else if (idx < WB_L2) {                 // layer l: [n=256][k=512]
        int r = idx - WB_LYR;
        int l = r >> 17;
        int q = r & 131071;
        int n = q >> 9, k = q & 511;
        float beta = logf((float)(l + 2) / (float)(l + 1));
        float omb = 1.0f - beta;
        if (k < 256) v = beta * w1[l * 65536 + k * 256 + n] + ((k == n) ? omb : 0.0f);
        else {
            int k2 = k - 256;
            v = beta * w2[l * 65536 + k2 * 256 + n] + ((k2 == n) ? omb : 0.0f);
        }
    } else {                                  // lin2: [n=128][k=256]
        int r = idx - WB_L2;
        int n = r >> 8, k = r & 255;
        v = lin2_w[k * 128 + n];
    }
    __nv_bfloat16 h, l;
    split2(v, h, l);
    g_Bw_hi[idx] = h;
    g_Bw_lo[idx] = l;
}
__global__ void k_prep_x(const float* __restrict__ x) {
    size_t idx = (size_t)blockIdx.x * blockDim.x + threadIdx.x;
    if (idx >= (size_t)NN * D_IN) return;
    __nv_bfloat16 h, l;
    split2(x[idx], h, l);
    g_xin_hi[idx] = h;
    g_xin_lo[idx] = l;
}

// ------------------------- SpMM with fused norm+relu on gather -----------
__global__ void __launch_bounds__(256) k_spmm(int l, const float* __restrict__ gam,
                                              const float* __restrict__ bet) {
    int par = l & 1;
    if (blockIdx.x == 0 && threadIdx.x == 0) { g_accA[par][0] = 0.0; g_accA[par][1] = 0.0; }
    int warp = (blockIdx.x * blockDim.x + threadIdx.x) >> 5;
    int lane = threadIdx.x & 31;
    if (warp >= NN) return;
    const float* __restrict__ h = (l == 0) ? g_x0 : g_h;

    float4 ca0, cb0, ca1, cb1;
    if (l == 0) {
        ca0 = ca1 = make_float4(1.f, 1.f, 1.f, 1.f);
        cb0 = cb1 = make_float4(0.f, 0.f, 0.f, 0.f);
    } else {
        int pp = (l - 1) & 1;
        double cnt = (double)NN * (double)D_HID;
        double mu = g_accA[pp][0] / cnt;
        double var = g_accA[pp][1] / cnt - mu * mu;
        if (var < 0.0) var = 0.0;
        float inv = (float)(1.0 / (sqrt(var) + 1e-5));
        float muf = (float)mu;
        int c0 = lane * 4, c1 = 128 + lane * 4;
        float4 g0 = *(const float4*)(gam + c0), g1 = *(const float4*)(gam + c1);
        float4 b0 = *(const float4*)(bet + c0), b1 = *(const float4*)(bet + c1);
        ca0 = make_float4(g0.x * inv, g0.y * inv, g0.z * inv, g0.w * inv);
        ca1 = make_float4(g1.x * inv, g1.y * inv, g1.z * inv, g1.w * inv);
        cb0 = make_float4(b0.x - muf * ca0.x, b0.y - muf * ca0.y, b0.z - muf * ca0.z, b0.w - muf * ca0.w);
        cb1 = make_float4(b1.x - muf * ca1.x, b1.y - muf * ca1.y, b1.z - muf * ca1.z, b1.w - muf * ca1.w);
    }

    int c = warp;
    float dc = g_dis[c];
    float wself = dc * dc;
    const float4* hr = (const float4*)(h + (size_t)c * D_HID);
    float4 v0 = hr[lane], v1 = hr[lane + 32];
    float4 a0, a1;
    a0.x = wself * fmaxf(ca0.x * v0.x + cb0.x, 0.f);
    a0.y = wself * fmaxf(ca0.y * v0.y + cb0.y, 0.f);
    a0.z = wself * fmaxf(ca0.z * v0.z + cb0.z, 0.f);
    a0.w = wself * fmaxf(ca0.w * v0.w + cb0.w, 0.f);
    a1.x = wself * fmaxf(ca1.x * v1.x + cb1.x, 0.f);
    a1.y = wself * fmaxf(ca1.y * v1.y + cb1.y, 0.f);
    a1.z = wself * fmaxf(ca1.z * v1.z + cb1.z, 0.f);
    a1.w = wself * fmaxf(ca1.w * v1.w + cb1.w, 0.f);

    int beg = g_rowptr[c], end = g_rowptr[c + 1];
#pragma unroll 4
    for (int e = beg; e < end; e++) {
        int   s = __ldg(&g_src[e]);
        float w = __ldg(&g_w[e]);
        const float4* hs = (const float4*)(h + (size_t)s * D_HID);
        float4 b0 = __ldg(&hs[lane]);
        float4 b1 = __ldg(&hs[lane + 32]);
        a0.x += w * fmaxf(ca0.x * b0.x + cb0.x, 0.f);
        a0.y += w * fmaxf(ca0.y * b0.y + cb0.y, 0.f);
        a0.z += w * fmaxf(ca0.z * b0.z + cb0.z, 0.f);
        a0.w += w * fmaxf(ca0.w * b0.w + cb0.w, 0.f);
        a1.x += w * fmaxf(ca1.x * b1.x + cb1.x, 0.f);
        a1.y += w * fmaxf(ca1.y * b1.y + cb1.y, 0.f);
        a1.z += w * fmaxf(ca1.z * b1.z + cb1.z, 0.f);
        a1.w += w * fmaxf(ca1.w * b1.w + cb1.w, 0.f);
    }
    __nv_bfloat16* Ah = g_A_hi + (size_t)c * 512;
    __nv_bfloat16* Al = g_A_lo + (size_t)c * 512;
    float vv[8] = {0.5f * a0.x, 0.5f * a0.y, 0.5f * a0.z, 0.5f * a0.w,
                   0.5f * a1.x, 0.5f * a1.y, 0.5f * a1.z, 0.5f * a1.w};
    int cols[2] = {lane * 4, 128 + lane * 4};
#pragma unroll
    for (int g = 0; g < 2; g++) {
        __nv_bfloat16 h4[4], l4[4];
#pragma unroll
        for (int j = 0; j < 4; j++) split2(vv[g * 4 + j], h4[j], l4[j]);
        *(__nv_bfloat162*)(Ah + cols[g])     = __nv_bfloat162(h4[0], h4[1]);
        *(__nv_bfloat162*)(Ah + cols[g] + 2) = __nv_bfloat162(h4[2], h4[3]);
        *(__nv_bfloat162*)(Al + cols[g])     = __nv_bfloat162(l4[0], l4[1]);
        *(__nv_bfloat162*)(Al + cols[g] + 2) = __nv_bfloat162(l4[2], l4[3]);
    }
}

// ------------------------- mma.sync GEMM (8 warps, 2-stage, 2 CTA/SM) ----
// mode 1: lin1   A=xin (lda=128), K=128    : relu(acc+bias)->g_x0 + 0.5x0 splits
// mode 2: layer  A=g_A (lda=512), K=512    : acc -> g_h + sums (W' pre-fused)
// mode 3: lin2   A=g_A (lda=512), K=256    : relu(acc+bias)->Cout
#define STG_SZ 40960
#define NSTG 2
#define SM_TOTAL (NSTG * STG_SZ)

__global__ void __launch_bounds__(256, 2) k_mma(int mode, int bOff, int K, int ldb, int N,
                                                const float* __restrict__ bias,
                                                float* __restrict__ Cout, int parity) {
    extern __shared__ char smem[];
    uint32_t sb = smem_u32(smem);
    int tid = threadIdx.x;
    int lane = tid & 31, wrp = tid >> 5;
    int wm = wrp & 1, wn = wrp >> 1;
    int m0 = blockIdx.y * 128, n0 = blockIdx.x * 128;

    const __nv_bfloat16* Ahi = (mode == 1) ? g_xin_hi : g_A_hi;
    const __nv_bfloat16* Alo = (mode == 1) ? g_xin_lo : g_A_lo;
    const int lda = (mode == 1) ? 128 : 512;
    const __nv_bfloat16* Bhi = g_Bw_hi + bOff;
    const __nv_bfloat16* Blo = g_Bw_lo + bOff;

    const int nch = K / 32;

    int r0i = tid >> 2, seg0 = (tid & 3);
    int r1i = (tid + 256) >> 2;

    auto load_stage = [&](int s, int ch) {
        int kb = ch * 32;
        uint32_t base = sb + s * STG_SZ;
        int gr0 = m0 + r0i; if (gr0 >= NN) gr0 = 0;
        int gr1 = m0 + r1i; if (gr1 >= NN) gr1 = 0;
        const __nv_bfloat16* a0h = Ahi + (size_t)gr0 * lda + kb + seg0 * 8;
        const __nv_bfloat16* a1h = Ahi + (size_t)gr1 * lda + kb + seg0 * 8;
        const __nv_bfloat16* a0l = Alo + (size_t)gr0 * lda + kb + seg0 * 8;
        const __nv_bfloat16* a1l = Alo + (size_t)gr1 * lda + kb + seg0 * 8;
        uint32_t d0 = base + r0i * 80 + seg0 * 16;
        uint32_t d1 = base + r1i * 80 + seg0 * 16;
        cp16(d0, a0h);          cp16(d1, a1h);
        cp16(d0 + 10240, a0l);  cp16(d1 + 10240, a1l);
        const __nv_bfloat16* b0h = Bhi + (size_t)(n0 + r0i) * ldb + kb + seg0 * 8;
        const __nv_bfloat16* b1h = Bhi + (size_t)(n0 + r1i) * ldb + kb + seg0 * 8;
        const __nv_bfloat16* b0l = Blo + (size_t)(n0 + r0i) * ldb + kb + seg0 * 8;
        const __nv_bfloat16* b1l = Blo + (size_t)(n0 + r1i) * ldb + kb + seg0 * 8;
        cp16(d0 + 20480, b0h);  cp16(d1 + 20480, b1h);
        cp16(d0 + 30720, b0l);  cp16(d1 + 30720, b1l);
    };

    float acc[4][4][4];
#pragma unroll
    for (int i = 0; i < 4; i++)
#pragma unroll
        for (int j = 0; j < 4; j++)
#pragma unroll
            for (int p = 0; p < 4; p++) acc[i][j][p] = 0.0f;

    load_stage(0, 0); CP_COMMIT();
    load_stage(1, 1); CP_COMMIT();

    int a_row = wm * 64 + (lane & 7) + ((lane >> 3) & 1) * 8;
    int a_colh = (lane >> 4) * 8;
    int b_row2 = wn * 32 + ((lane >> 4) & 1) * 8 + (lane & 7);
    int b_colh = ((lane >> 3) & 1) * 8;

    for (int ch = 0; ch < nch; ch++) {
        int st = ch & 1;
        CP_WAIT1();
        __syncthreads();
        uint32_t base = sb + st * STG_SZ;
#pragma unroll
        for (int k16 = 0; k16 < 2; k16++) {
            uint32_t ah[4][4], al[4][4], bh[4][2], bl[4][2];
#pragma unroll
            for (int mt = 0; mt < 4; mt++) {
                uint32_t ad = base + (a_row + mt * 16) * 80 + (k16 * 16 + a_colh) * 2;
                ldm_x4(ah[mt], ad);
                ldm_x4(al[mt], ad + 10240);
            }
#pragma unroll
            for (int np = 0; np < 2; np++) {
                uint32_t bd = base + 20480 + (b_row2 + np * 16) * 80 + (k16 * 16 + b_colh) * 2;
                uint32_t r4[4];
                ldm_x4(r4, bd);
                bh[np * 2][0] = r4[0]; bh[np * 2][1] = r4[1];
                bh[np * 2 + 1][0] = r4[2]; bh[np * 2 + 1][1] = r4[3];
                ldm_x4(r4, bd + 10240);
                bl[np * 2][0] = r4[0]; bl[np * 2][1] = r4[1];
                bl[np * 2 + 1][0] = r4[2]; bl[np * 2 + 1][1] = r4[3];
            }
#pragma unroll
            for (int mt = 0; mt < 4; mt++)
#pragma unroll
                for (int nt = 0; nt < 4; nt++) {
                    mma16816(acc[mt][nt], ah[mt], bh[nt]);
                    mma16816(acc[mt][nt], al[mt], bh[nt]);
                    mma16816(acc[mt][nt], ah[mt], bl[nt]);
                }
        }
        __syncthreads();
        if (ch + 2 < nch) load_stage(st, ch + 2);
        CP_COMMIT();
    }

    // ------------- epilogue -------------
    float sum = 0.0f, ssum = 0.0f;
    int rbase = m0 + wm * 64 + (lane >> 2);
    int cbase = n0 + wn * 32 + (lane & 3) * 2;
#pragma unroll
    for (int mt = 0; mt < 4; mt++) {
#pragma unroll
        for (int half = 0; half < 2; half++) {
            int row = rbase + mt * 16 + half * 8;
            if (row >= NN) continue;
#pragma unroll
            for (int nt = 0; nt < 4; nt++) {
                int c = cbase + nt * 8;
                float v0 = acc[mt][nt][half * 2 + 0];
                float v1 = acc[mt][nt][half * 2 + 1];
                if (mode == 2) {
                    size_t idx = (size_t)row * 256 + c;
                    *(float2*)(g_h + idx) = make_float2(v0, v1);
                    sum += v0 + v1;
                    ssum += v0 * v0 + v1 * v1;
                } else if (mode == 1) {
                    float r0 = fmaxf(v0 + __ldg(&bias[c]), 0.0f);
                    float r1 = fmaxf(v1 + __ldg(&bias[c + 1]), 0.0f);
                    *(float2*)(g_x0 + (size_t)row * 256 + c) = make_float2(r0, r1);
                    __nv_bfloat16 h0, l0, h1, l1;
                    split2(0.5f * r0, h0, l0);
                    split2(0.5f * r1, h1, l1);
                    size_t sidx = (size_t)row * 512 + 256 + c;
                    *(__nv_bfloat162*)(g_A_hi + sidx) = __nv_bfloat162(h0, h1);
                    *(__nv_bfloat162*)(g_A_lo + sidx) = __nv_bfloat162(l0, l1);
                } else {
                    float r0 = fmaxf(v0 + __ldg(&bias[c]), 0.0f);
                    float r1 = fmaxf(v1 + __ldg(&bias[c + 1]), 0.0f);
                    *(float2*)(Cout + (size_t)row * N + c) = make_float2(r0, r1);
                }
            }
        }
    }
    if (mode == 2) {
#pragma unroll
        for (int off = 16; off > 0; off >>= 1) {
            sum  += __shfl_down_sync(0xffffffffu, sum, off);
            ssum += __shfl_down_sync(0xffffffffu, ssum, off);
        }
        __syncthreads();
        float* rs  = (float*)smem;
        float* rss = (float*)smem + 32;
        if (lane == 0) { rs[wrp] = sum; rss[wrp] = ssum; }
        __syncthreads();
        if (tid == 0) {
            float S = 0.f, SS = 0.f;
            for (int w = 0; w < 8; w++) { S += rs[w]; SS += rss[w]; }
            atomicAdd(&g_accA[parity][0], (double)S);
            atomicAdd(&g_accA[parity][1], (double)SS);
        }
    }
}

// ------------------------- final norm -> lin2 input splits ---------------
__global__ void k_norm_final(const float* __restrict__ gam, const float* __restrict__ bet) {
    double cnt = (double)NN * (double)D_HID;
    double mu = g_accA[1][0] / cnt;
    double var = g_accA[1][1] / cnt - mu * mu;
    if (var < 0.0) var = 0.0;
    float inv = (float)(1.0 / (sqrt(var) + 1e-5));
    float muf = (float)mu;
    size_t total = (size_t)NN * D_HID / 4;
    size_t i = (size_t)blockIdx.x * blockDim.x + threadIdx.x;
    if (i >= total) return;
    float4 v = ((const float4*)g_h)[i];
    int c = (int)((i * 4) & (D_HID - 1));
    float4 gg = *(const float4*)(gam + c);
    float4 bb = *(const float4*)(bet + c);
    float r0 = fmaxf(gg.x * ((v.x - muf) * inv) + bb.x, 0.0f);
    float r1 = fmaxf(gg.y * ((v.y - muf) * inv) + bb.y, 0.0f);
    float r2 = fmaxf(gg.z * ((v.z - muf) * inv) + bb.z, 0.0f);
    float r3 = fmaxf(gg.w * ((v.w - muf) * inv) + bb.w, 0.0f);
    size_t row = (i * 4) >> 8;
    size_t base = row * 512 + c;
    __nv_bfloat16 h4[4], l4[4];
    split2(r0, h4[0], l4[0]); split2(r1, h4[1], l4[1]);
    split2(r2, h4[2], l4[2]); split2(r3, h4[3], l4[3]);
    *(__nv_bfloat162*)(g_A_hi + base)     = __nv_bfloat162(h4[0], h4[1]);
    *(__nv_bfloat162*)(g_A_hi + base + 2) = __nv_bfloat162(h4[2], h4[3]);
    *(__nv_bfloat162*)(g_A_lo + base)     = __nv_bfloat162(l4[0], l4[1]);
    *(__nv_bfloat162*)(g_A_lo + base + 2) = __nv_bfloat162(l4[2], l4[3]);
}

// ------------------------- launch -------------------------
extern "C" void kernel_launch(void* const* d_in, const int* in_sizes, int n_in,
                              void* d_out, int out_size) {
    const float* x       = (const float*)d_in[0];
    const int*   ei      = (const int*)  d_in[1];
    const float* lin1_w  = (const float*)d_in[2];
    const float* lin1_b  = (const float*)d_in[3];
    const float* conv_w1 = (const float*)d_in[4];
    const float* conv_w2 = (const float*)d_in[5];
    const float* gamma   = (const float*)d_in[6];
    const float* betaa   = (const float*)d_in[7];
    const float* lin2_w  = (const float*)d_in[8];
    const float* lin2_b  = (const float*)d_in[9];
    float* out = (float*)d_out;

    static int smem_set = 0;
    if (!smem_set) {
        cudaFuncSetAttribute(k_mma, cudaFuncAttributeMaxDynamicSharedMemorySize, SM_TOTAL);
        smem_set = 1;
    }

    // CSR build (by destination) + deg^{-1/2}
    k_zero<<<(NN + 255) / 256, 256>>>();
    k_count<<<(NE + 255) / 256, 256>>>(ei);
    k_scan_part<<<49, 1024>>>();
    k_scan_top<<<1, 32>>>();
    k_scan_out<<<49, 1024>>>();
    k_scatter<<<(NE + 255) / 256, 256>>>(ei);

    // bf16 operand prep
    k_prep_w<<<(WB_TOT + 255) / 256, 256>>>(lin1_w, conv_w1, conv_w2, lin2_w);
    k_prep_x<<<(NN * D_IN + 255) / 256, 256>>>(x);

    const int MT = (NN + 127) / 128;  // 391

    // lin1 + relu -> g_x0 (+ 0.5*x0 splits)
    k_mma<<<dim3(2, MT), 256, SM_TOTAL>>>(1, WB_L1, 128, 128, 256, lin1_b, nullptr, 0);

    // 8 GCNII layers: SpMM(fused prev-norm) -> GEMM K=512 (W' pre-fused)
    for (int l = 0; l < NL; l++) {
        k_spmm<<<(NN + 7) / 8, 256>>>(l, gamma + (size_t)(l > 0 ? l - 1 : 0) * D_HID,
                                      betaa + (size_t)(l > 0 ? l - 1 : 0) * D_HID);
        k_mma<<<dim3(2, MT), 256, SM_TOTAL>>>(2, WB_LYR + l * 131072, 512, 512, 256,
                                              nullptr, nullptr, l & 1);
    }

    // final norm (layer 7 params) -> lin2 input splits
    k_norm_final<<<(NN * D_HID / 4 + 255) / 256, 256>>>(gamma + 7 * (size_t)D_HID,
                                                        betaa + 7 * (size_t)D_HID);

    // lin2 + relu -> out
    k_mma<<<dim3(1, MT), 256, SM_TOTAL>>>(3, WB_L2, 256, 256, 128, lin2_b, out, 0);

    (void)in_sizes; (void)n_in; (void)out_size;
}

// round 10
// speedup vs baseline: 1.7749x; 1.0157x over previous
#include <cuda_runtime.h>
#include <cuda_bf16.h>
#include <cuda_fp16.h>
#include <math.h>
#include <stdint.h>

#define NN   50000
#define NE   800000
#define D_IN 128
#define D_HID 256
#define D_OUT 128
#define NL   8

// ---------------- weight buffer layout (transposed, K-major [N][K]) ------
#define WB_L1   0                         // lin1: [256][128]
#define WB_LYR  32768                     // layers: 8 x [256][512]  (W' = beta*W + omb*I)
#define WB_L2   (32768 + 8 * 131072)      // lin2: [128][256]
#define WB_TOT  (WB_L2 + 32768)

// ------------------------- static device scratch -------------------------
__device__ float  g_dis[NN];
__device__ int    g_rowptr[NN + 1];
__device__ int    g_cnt[NN];
__device__ int    g_bsum[64];
__device__ int    g_boff[64];
__device__ int    g_src[NE];
__device__ float  g_w[NE];
__device__ __half g_hh[(size_t)NN * D_HID];          // fp16 h (or x0) for gather
__device__ double g_accA[2][2];                      // [parity][sum, sumsq]
// bf16 split operands
__device__ __nv_bfloat16 g_A_hi[(size_t)NN * 512];   // cols 0..255: t (or h_norm) ; 256..511: 0.5*x0
__device__ __nv_bfloat16 g_A_lo[(size_t)NN * 512];
__device__ __nv_bfloat16 g_xin_hi[(size_t)NN * D_IN];
__device__ __nv_bfloat16 g_xin_lo[(size_t)NN * D_IN];
__device__ __nv_bfloat16 g_Bw_hi[WB_TOT];
__device__ __nv_bfloat16 g_Bw_lo[WB_TOT];

// ------------------------- helpers -------------------------
__device__ __forceinline__ uint32_t smem_u32(const void* p) {
    uint32_t a;
    asm("{ .reg .u64 t; cvta.to.shared.u64 t, %1; cvt.u32.u64 %0, t; }" : "=r"(a) : "l"(p));
    return a;
}
__device__ __forceinline__ void cp16(uint32_t dst, const void* src) {
    asm volatile("cp.async.cg.shared.global [%0], [%1], 16;" :: "r"(dst), "l"(src));
}
#define CP_COMMIT() asm volatile("cp.async.commit_group;" ::: "memory")
#define CP_WAIT1()  asm volatile("cp.async.wait_group 1;" ::: "memory")

__device__ __forceinline__ void ldm_x4(uint32_t* r, uint32_t addr) {
    asm volatile("ldmatrix.sync.aligned.m8n8.x4.shared.b16 {%0,%1,%2,%3}, [%4];"
                 : "=r"(r[0]), "=r"(r[1]), "=r"(r[2]), "=r"(r[3]) : "r"(addr));
}
__device__ __forceinline__ void mma16816(float* c, const uint32_t* a, const uint32_t* b) {
    asm volatile("mma.sync.aligned.m16n8k16.row.col.f32.bf16.bf16.f32 "
                 "{%0,%1,%2,%3}, {%4,%5,%6,%7}, {%8,%9}, {%0,%1,%2,%3};"
                 : "+f"(c[0]), "+f"(c[1]), "+f"(c[2]), "+f"(c[3])
                 : "r"(a[0]), "r"(a[1]), "r"(a[2]), "r"(a[3]), "r"(b[0]), "r"(b[1]));
}
__device__ __forceinline__ void split2(float v, __nv_bfloat16& h, __nv_bfloat16& l) {
    h = __float2bfloat16(v);
    l = __float2bfloat16(v - __bfloat162float(h));
}

// ------------------------- setup kernels -------------------------
__global__ void k_zero() {
    int i = blockIdx.x * blockDim.x + threadIdx.x;
    if (i < NN) g_cnt[i] = 0;
}
__global__ void k_count(const int* __restrict__ ei) {
    int e = blockIdx.x * blockDim.x + threadIdx.x;
    if (e < NE) atomicAdd(&g_cnt[ei[NE + e]], 1);
}
__device__ __forceinline__ int block_scan_inc(int v, int* wsum) {
    int lane = threadIdx.x & 31, wid = threadIdx.x >> 5;
#pragma unroll
    for (int o = 1; o < 32; o <<= 1) { int t = __shfl_up_sync(~0u, v, o); if (lane >= o) v += t; }
    if (lane == 31) wsum[wid] = v;
    __syncthreads();
    if (wid == 0) {
        int w = wsum[lane];
#pragma unroll
        for (int o = 1; o < 32; o <<= 1) { int t = __shfl_up_sync(~0u, w, o); if (lane >= o) w += t; }
        wsum[lane] = w;
    }
    __syncthreads();
    return v + (wid > 0 ? wsum[wid - 1] : 0);
}
__global__ void k_scan_part() {
    __shared__ int wsum[32];
    int i = blockIdx.x * 1024 + threadIdx.x;
    int v = (i < NN) ? g_cnt[i] : 0;
    int inc = block_scan_inc(v, wsum);
    if (threadIdx.x == 1023) g_bsum[blockIdx.x] = inc;
}
__global__ void k_scan_top() {
    int lane = threadIdx.x;
    int v0 = (lane < 49) ? g_bsum[lane] : 0;
    int v1 = (lane + 32 < 49) ? g_bsum[lane + 32] : 0;
    int s0 = v0;
#pragma unroll
    for (int o = 1; o < 32; o <<= 1) { int t = __shfl_up_sync(~0u, s0, o); if (lane >= o) s0 += t; }
    int tot0 = __shfl_sync(~0u, s0, 31);
    int s1 = v1;
#pragma unroll
    for (int o = 1; o < 32; o <<= 1) { int t = __shfl_up_sync(~0u, s1, o); if (lane >= o) s1 += t; }
    int tot1 = __shfl_sync(~0u, s1, 31);
    g_boff[lane] = s0 - v0;
    if (lane + 32 < 49) g_boff[lane + 32] = tot0 + s1 - v1;
    if (lane == 0) g_rowptr[NN] = tot0 + tot1;
}
__global__ void k_scan_out() {
    __shared__ int wsum[32];
    int i = blockIdx.x * 1024 + threadIdx.x;
    int v = (i < NN) ? g_cnt[i] : 0;
    int inc = block_scan_inc(v, wsum);
    if (i < NN) {
        int rp = g_boff[blockIdx.x] + inc - v;
        g_rowptr[i] = rp;
        g_cnt[i] = rp;
        g_dis[i] = rsqrtf((float)(v + 1));
    }
}
__global__ void k_scatter(const int* __restrict__ ei) {
    int e = blockIdx.x * blockDim.x + threadIdx.x;
    if (e < NE) {
        int r = ei[e];
        int c = ei[NE + e];
        int s = atomicAdd(&g_cnt[c], 1);
        g_src[s] = r;
        g_w[s]   = g_dis[r] * g_dis[c];
    }
}

// ------------------------- weight / input prep (bf16 splits) -------------
__global__ void k_prep_w(const float* __restrict__ lin1_w, const float* __restrict__ w1,
                         const float* __restrict__ w2, const float* __restrict__ lin2_w) {
    int idx = blockIdx.x * blockDim.x + threadIdx.x;
    if (idx >= WB_TOT) return;
    float v;
    if (idx < WB_LYR) {
        int n = idx >> 7, k = idx & 127;
        v = lin1_w[k * 256 + n];
    } else if (idx < WB_L2) {
        int r = idx - WB_LYR;
        int l = r >> 17;
        int q = r & 131071;
        int n = q >> 9, k = q & 511;
        float beta = logf((float)(l + 2) / (float)(l + 1));
        float omb = 1.0f - beta;
        if (k < 256) v = beta * w1[l * 65536 + k * 256 + n] + ((k == n) ? omb : 0.0f);
        else {
            int k2 = k - 256;
            v = beta * w2[l * 65536 + k2 * 256 + n] + ((k2 == n) ? omb : 0.0f);
        }
    } else {
        int r = idx - WB_L2;
        int n = r >> 8, k = r & 255;
        v = lin2_w[k * 128 + n];
    }
    __nv_bfloat16 h, l;
    split2(v, h, l);
    g_Bw_hi[idx] = h;
    g_Bw_lo[idx] = l;
}
__global__ void k_prep_x(const float* __restrict__ x) {
    size_t idx = (size_t)blockIdx.x * blockDim.x + threadIdx.x;
    if (idx >= (size_t)NN * D_IN) return;
    __nv_bfloat16 h, l;
    split2(x[idx], h, l);
    g_xin_hi[idx] = h;
    g_xin_lo[idx] = l;
}

// ------------------------- SpMM (fp16 gather, fused norm+relu) -----------
// lane owns 8 contiguous cols [lane*8, lane*8+8): one uint4 (16B) per edge.
__global__ void __launch_bounds__(256) k_spmm(int l, const float* __restrict__ gam,
                                              const float* __restrict__ bet) {
    int par = l & 1;
    if (blockIdx.x == 0 && threadIdx.x == 0) { g_accA[par][0] = 0.0; g_accA[par][1] = 0.0; }
    int warp = (blockIdx.x * blockDim.x + threadIdx.x) >> 5;
    int lane = threadIdx.x & 31;
    if (warp >= NN) return;

    // per-lane norm coefficients for 8 owned columns
    float ca[8], cb[8];
    if (l == 0) {
#pragma unroll
        for (int j = 0; j < 8; j++) { ca[j] = 1.0f; cb[j] = 0.0f; }
    } else {
        int pp = (l - 1) & 1;
        double cnt = (double)NN * (double)D_HID;
        double mu = g_accA[pp][0] / cnt;
        double var = g_accA[pp][1] / cnt - mu * mu;
        if (var < 0.0) var = 0.0;
        float inv = (float)(1.0 / (sqrt(var) + 1e-5));
        float muf = (float)mu;
        int c0 = lane * 8;
        float4 ga = *(const float4*)(gam + c0);
        float4 gb = *(const float4*)(gam + c0 + 4);
        float4 ba = *(const float4*)(bet + c0);
        float4 bb = *(const float4*)(bet + c0 + 4);
        float gv[8] = {ga.x, ga.y, ga.z, ga.w, gb.x, gb.y, gb.z, gb.w};
        float bv[8] = {ba.x, ba.y, ba.z, ba.w, bb.x, bb.y, bb.z, bb.w};
#pragma unroll
        for (int j = 0; j < 8; j++) { ca[j] = gv[j] * inv; cb[j] = bv[j] - muf * ca[j]; }
    }

    int c = warp;
    float dc = g_dis[c];
    float wself = dc * dc;
    float acc[8];
    {
        uint4 q = __ldg((const uint4*)(g_hh + (size_t)c * D_HID + lane * 8));
        __half2 p0 = *(__half2*)&q.x, p1 = *(__half2*)&q.y;
        __half2 p2 = *(__half2*)&q.z, p3 = *(__half2*)&q.w;
        float2 f0 = __half22float2(p0), f1 = __half22float2(p1);
        float2 f2 = __half22float2(p2), f3 = __half22float2(p3);
        float v[8] = {f0.x, f0.y, f1.x, f1.y, f2.x, f2.y, f3.x, f3.y};
#pragma unroll
        for (int j = 0; j < 8; j++) acc[j] = wself * fmaxf(ca[j] * v[j] + cb[j], 0.0f);
    }

    int beg = g_rowptr[c], end = g_rowptr[c + 1];
#pragma unroll 4
    for (int e = beg; e < end; e++) {
        int   s = __ldg(&g_src[e]);
        float w = __ldg(&g_w[e]);
        uint4 q = __ldg((const uint4*)(g_hh + (size_t)s * D_HID + lane * 8));
        __half2 p0 = *(__half2*)&q.x, p1 = *(__half2*)&q.y;
        __half2 p2 = *(__half2*)&q.z, p3 = *(__half2*)&q.w;
        float2 f0 = __half22float2(p0), f1 = __half22float2(p1);
        float2 f2 = __half22float2(p2), f3 = __half22float2(p3);
        float v[8] = {f0.x, f0.y, f1.x, f1.y, f2.x, f2.y, f3.x, f3.y};
#pragma unroll
        for (int j = 0; j < 8; j++) acc[j] += w * fmaxf(ca[j] * v[j] + cb[j], 0.0f);
    }

    // t = 0.5 * agg -> bf16 splits (16B store each)
    __nv_bfloat16 h8[8], l8[8];
#pragma unroll
    for (int j = 0; j < 8; j++) split2(0.5f * acc[j], h8[j], l8[j]);
    size_t base = (size_t)c * 512 + lane * 8;
    *(uint4*)(g_A_hi + base) = *(uint4*)h8;
    *(uint4*)(g_A_lo + base) = *(uint4*)l8;
}

// ------------------------- mma.sync GEMM (8 warps, 2-stage, 2 CTA/SM) ----
// mode 1: lin1   A=xin (lda=128), K=128 : relu(acc+bias) -> g_hh(half) + 0.5x0 splits
// mode 2: layer  A=g_A (lda=512), K=512 : acc -> g_hh(half) + fp32 stats
// mode 3: lin2   A=g_A (lda=512), K=256 : relu(acc+bias) -> Cout
#define STG_SZ 40960
#define NSTG 2
#define SM_TOTAL (NSTG * STG_SZ)

__global__ void __launch_bounds__(256, 2) k_mma(int mode, int bOff, int K, int ldb, int N,
                                                const float* __restrict__ bias,
                                                float* __restrict__ Cout, int parity) {
    extern __shared__ char smem[];
    uint32_t sb = smem_u32(smem);
    int tid = threadIdx.x;
    int lane = tid & 31, wrp = tid >> 5;
    int wm = wrp & 1, wn = wrp >> 1;
    int m0 = blockIdx.y * 128, n0 = blockIdx.x * 128;

    const __nv_bfloat16* Ahi = (mode == 1) ? g_xin_hi : g_A_hi;
    const __nv_bfloat16* Alo = (mode == 1) ? g_xin_lo : g_A_lo;
    const int lda = (mode == 1) ? 128 : 512;
    const __nv_bfloat16* Bhi = g_Bw_hi + bOff;
    const __nv_bfloat16* Blo = g_Bw_lo + bOff;

    const int nch = K / 32;

    int r0i = tid >> 2, seg0 = (tid & 3);
    int r1i = (tid + 256) >> 2;

    auto load_stage = [&](int s, int ch) {
        int kb = ch * 32;
        uint32_t base = sb + s * STG_SZ;
        int gr0 = m0 + r0i; if (gr0 >= NN) gr0 = 0;
        int gr1 = m0 + r1i; if (gr1 >= NN) gr1 = 0;
        const __nv_bfloat16* a0h = Ahi + (size_t)gr0 * lda + kb + seg0 * 8;
        const __nv_bfloat16* a1h = Ahi + (size_t)gr1 * lda + kb + seg0 * 8;
        const __nv_bfloat16* a0l = Alo + (size_t)gr0 * lda + kb + seg0 * 8;
        const __nv_bfloat16* a1l = Alo + (size_t)gr1 * lda + kb + seg0 * 8;
        uint32_t d0 = base + r0i * 80 + seg0 * 16;
        uint32_t d1 = base + r1i * 80 + seg0 * 16;
        cp16(d0, a0h);          cp16(d1, a1h);
        cp16(d0 + 10240, a0l);  cp16(d1 + 10240, a1l);
        const __nv_bfloat16* b0h = Bhi + (size_t)(n0 + r0i) * ldb + kb + seg0 * 8;
        const __nv_bfloat16* b1h = Bhi + (size_t)(n0 + r1i) * ldb + kb + seg0 * 8;
        const __nv_bfloat16* b0l = Blo + (size_t)(n0 + r0i) * ldb + kb + seg0 * 8;
        const __nv_bfloat16* b1l = Blo + (size_t)(n0 + r1i) * ldb + kb + seg0 * 8;
        cp16(d0 + 20480, b0h);  cp16(d1 + 20480, b1h);
        cp16(d0 + 30720, b0l);  cp16(d1 + 30720, b1l);
    };

    float acc[4][4][4];
#pragma unroll
    for (int i = 0; i < 4; i++)
#pragma unroll
        for (int j = 0; j < 4; j++)
#pragma unroll
            for (int p = 0; p < 4; p++) acc[i][j][p] = 0.0f;

    load_stage(0, 0); CP_COMMIT();
    load_stage(1, 1); CP_COMMIT();

    int a_row = wm * 64 + (lane & 7) + ((lane >> 3) & 1) * 8;
    int a_colh = (lane >> 4) * 8;
    int b_row2 = wn * 32 + ((lane >> 4) & 1) * 8 + (lane & 7);
    int b_colh = ((lane >> 3) & 1) * 8;

    for (int ch = 0; ch < nch; ch++) {
        int st = ch & 1;
        CP_WAIT1();
        __syncthreads();
        uint32_t base = sb + st * STG_SZ;
#pragma unroll
        for (int k16 = 0; k16 < 2; k16++) {
            uint32_t ah[4][4], al[4][4], bh[4][2], bl[4][2];
#pragma unroll
            for (int mt = 0; mt < 4; mt++) {
                uint32_t ad = base + (a_row + mt * 16) * 80 + (k16 * 16 + a_colh) * 2;
                ldm_x4(ah[mt], ad);
                ldm_x4(al[mt], ad + 10240);
            }
#pragma unroll
            for (int np = 0; np < 2; np++) {
                uint32_t bd = base + 20480 + (b_row2 + np * 16) * 80 + (k16 * 16 + b_colh) * 2;
                uint32_t r4[4];
                ldm_x4(r4, bd);
                bh[np * 2][0] = r4[0]; bh[np * 2][1] = r4[1];
                bh[np * 2 + 1][0] = r4[2]; bh[np * 2 + 1][1] = r4[3];
                ldm_x4(r4, bd + 10240);
                bl[np * 2][0] = r4[0]; bl[np * 2][1] = r4[1];
                bl[np * 2 + 1][0] = r4[2]; bl[np * 2 + 1][1] = r4[3];
            }
#pragma unroll
            for (int mt = 0; mt < 4; mt++)
#pragma unroll
                for (int nt = 0; nt < 4; nt++) {
                    mma16816(acc[mt][nt], ah[mt], bh[nt]);
                    mma16816(acc[mt][nt], al[mt], bh[nt]);
                    mma16816(acc[mt][nt], ah[mt], bl[nt]);
                }
        }
        __syncthreads();
        if (ch + 2 < nch) load_stage(st, ch + 2);
        CP_COMMIT();
    }

    // ------------- epilogue -------------
    float sum = 0.0f, ssum = 0.0f;
    int rbase = m0 + wm * 64 + (lane >> 2);
    int cbase = n0 + wn * 32 + (lane & 3) * 2;
#pragma unroll
    for (int mt = 0; mt < 4; mt++) {
#pragma unroll
        for (int half = 0; half < 2; half++) {
            int row = rbase + mt * 16 + half * 8;
            if (row >= NN) continue;
#pragma unroll
            for (int nt = 0; nt < 4; nt++) {
                int c = cbase + nt * 8;
                float v0 = acc[mt][nt][half * 2 + 0];
                float v1 = acc[mt][nt][half * 2 + 1];
                if (mode == 2) {
                    *(__half2*)(g_hh + (size_t)row * 256 + c) = __floats2half2_rn(v0, v1);
                    sum += v0 + v1;
                    ssum += v0 * v0 + v1 * v1;
                } else if (mode == 1) {
                    float r0 = fmaxf(v0 + __ldg(&bias[c]), 0.0f);
                    float r1 = fmaxf(v1 + __ldg(&bias[c + 1]), 0.0f);
                    *(__half2*)(g_hh + (size_t)row * 256 + c) = __floats2half2_rn(r0, r1);
                    __nv_bfloat16 h0, l0, h1, l1;
                    split2(0.5f * r0, h0, l0);
                    split2(0.5f * r1, h1, l1);
                    size_t sidx = (size_t)row * 512 + 256 + c;
                    *(__nv_bfloat162*)(g_A_hi + sidx) = __nv_bfloat162(h0, h1);
                    *(__nv_bfloat162*)(g_A_lo + sidx) = __nv_bfloat162(l0, l1);
                } else {
                    float r0 = fmaxf(v0 + __ldg(&bias[c]), 0.0f);
                    float r1 = fmaxf(v1 + __ldg(&bias[c + 1]), 0.0f);
                    *(float2*)(Cout + (size_t)row * N + c) = make_float2(r0, r1);
                }
            }
        }
    }
    if (mode == 2) {
#pragma unroll
        for (int off = 16; off > 0; off >>= 1) {
            sum  += __shfl_down_sync(0xffffffffu, sum, off);
            ssum += __shfl_down_sync(0xffffffffu, ssum, off);
        }
        __syncthreads();
        float* rs  = (float*)smem;
        float* rss = (float*)smem + 32;
        if (lane == 0) { rs[wrp] = sum; rss[wrp] = ssum; }
        __syncthreads();
        if (tid == 0) {
            float S = 0.f, SS = 0.f;
            for (int w = 0; w < 8; w++) { S += rs[w]; SS += rss[w]; }
            atomicAdd(&g_accA[parity][0], (double)S);
            atomicAdd(&g_accA[parity][1], (double)SS);
        }
    }
}

// ------------------------- final norm -> lin2 input splits ---------------
__global__ void k_norm_final(const float* __restrict__ gam, const float* __restrict__ bet) {
    double cnt = (double)NN * (double)D_HID;
    double mu = g_accA[1][0] / cnt;
    double var = g_accA[1][1] / cnt - mu * mu;
    if (var < 0.0) var = 0.0;
    float inv = (float)(1.0 / (sqrt(var) + 1e-5));
    float muf = (float)mu;
    size_t total = (size_t)NN * D_HID / 4;
    size_t i = (size_t)blockIdx.x * blockDim.x + threadIdx.x;
    if (i >= total) return;
    uint2 q = *(const uint2*)(g_hh + i * 4);
    float2 f0 = __half22float2(*(__half2*)&q.x);
    float2 f1 = __half22float2(*(__half2*)&q.y);
    int c = (int)((i * 4) & (D_HID - 1));
    float4 gg = *(const float4*)(gam + c);
    float4 bb = *(const float4*)(bet + c);
    float r0 = fmaxf(gg.x * ((f0.x - muf) * inv) + bb.x, 0.0f);
    float r1 = fmaxf(gg.y * ((f0.y - muf) * inv) + bb.y, 0.0f);
    float r2 = fmaxf(gg.z * ((f1.x - muf) * inv) + bb.z, 0.0f);
    float r3 = fmaxf(gg.w * ((f1.y - muf) * inv) + bb.w, 0.0f);
    size_t row = (i * 4) >> 8;
    size_t base = row * 512 + c;
    __nv_bfloat16 h4[4], l4[4];
    split2(r0, h4[0], l4[0]); split2(r1, h4[1], l4[1]);
    split2(r2, h4[2], l4[2]); split2(r3, h4[3], l4[3]);
    *(__nv_bfloat162*)(g_A_hi + base)     = __nv_bfloat162(h4[0], h4[1]);
    *(__nv_bfloat162*)(g_A_hi + base + 2) = __nv_bfloat162(h4[2], h4[3]);
    *(__nv_bfloat162*)(g_A_lo + base)     = __nv_bfloat162(l4[0], l4[1]);
    *(__nv_bfloat162*)(g_A_lo + base + 2) = __nv_bfloat162(l4[2], l4[3]);
}

// ------------------------- launch -------------------------
extern "C" void kernel_launch(void* const* d_in, const int* in_sizes, int n_in,
                              void* d_out, int out_size) {
    const float* x       = (const float*)d_in[0];
    const int*   ei      = (const int*)  d_in[1];
    const float* lin1_w  = (const float*)d_in[2];
    const float* lin1_b  = (const float*)d_in[3];
    const float* conv_w1 = (const float*)d_in[4];
    const float* conv_w2 = (const float*)d_in[5];
    const float* gamma   = (const float*)d_in[6];
    const float* betaa   = (const float*)d_in[7];
    const float* lin2_w  = (const float*)d_in[8];
    const float* lin2_b  = (const float*)d_in[9];
    float* out = (float*)d_out;

    static int smem_set = 0;
    if (!smem_set) {
        cudaFuncSetAttribute(k_mma, cudaFuncAttributeMaxDynamicSharedMemorySize, SM_TOTAL);
        smem_set = 1;
    }

    // CSR build (by destination) + deg^{-1/2}
    k_zero<<<(NN + 255) / 256, 256>>>();
    k_count<<<(NE + 255) / 256, 256>>>(ei);
    k_scan_part<<<49, 1024>>>();
    k_scan_top<<<1, 32>>>();
    k_scan_out<<<49, 1024>>>();
    k_scatter<<<(NE + 255) / 256, 256>>>(ei);

    // bf16 operand prep
    k_prep_w<<<(WB_TOT + 255) / 256, 256>>>(lin1_w, conv_w1, conv_w2, lin2_w);
    k_prep_x<<<(NN * D_IN + 255) / 256, 256>>>(x);

    const int MT = (NN + 127) / 128;  // 391

    // lin1 + relu -> g_hh (half) + 0.5*x0 splits
    k_mma<<<dim3(2, MT), 256, SM_TOTAL>>>(1, WB_L1, 128, 128, 256, lin1_b, nullptr, 0);

    // 8 GCNII layers: SpMM(fused prev-norm, fp16 gather) -> GEMM K=512
    for (int l = 0; l < NL; l++) {
        k_spmm<<<(NN + 7) / 8, 256>>>(l, gamma + (size_t)(l > 0 ? l - 1 : 0) * D_HID,
                                      betaa + (size_t)(l > 0 ? l - 1 : 0) * D_HID);
        k_mma<<<dim3(2, MT), 256, SM_TOTAL>>>(2, WB_LYR + l * 131072, 512, 512, 256,
                                              nullptr, nullptr, l & 1);
    }

    // final norm (layer 7 params) -> lin2 input splits
    k_norm_final<<<(NN * D_HID / 4 + 255) / 256, 256>>>(gamma + 7 * (size_t)D_HID,
                                                        betaa + 7 * (size_t)D_HID);

    // lin2 + relu -> out
    k_mma<<<dim3(1, MT), 256, SM_TOTAL>>>(3, WB_L2, 256, 256, 128, lin2_b, out, 0);

    (void)in_sizes; (void)n_in; (void)out_size;
}